// round 2
// baseline (speedup 1.0000x reference)
#include <cuda_runtime.h>
#include <math.h>

#define BB 8
#define CC 256
#define SS 16384
#define EPSV 1e-5f

// ---------------- scratch (static device globals; ~9 MB) ----------------
__device__ float g_G [BB*CC*CC];   // X X^T per batch (symmetric)
__device__ float g_P [BB*CC*CC];   // Aq @ G
__device__ float g_L [BB*CC*CC];   // logits -> attn (in place)
__device__ float g_M [BB*CC*CC];   // attn @ Av + I
__device__ float g_Aq[CC*CC];
__device__ float g_Ak[CC*CC];
__device__ float g_AvT[CC*CC];     // Av stored transposed
__device__ float g_bq[CC];
__device__ float g_bk[CC];
__device__ float g_bv[CC];
__device__ float g_s [BB*CC];      // row sums of X
__device__ float g_u [BB*CC];      // Aq @ s
__device__ float g_w [BB*CC];      // Ak @ s
__device__ float g_cv[BB*CC];      // attn @ bv

// ---------------- reductions ----------------
__device__ __forceinline__ float blockReduceSum(float v) {
    __shared__ float sh[8];
    int lane = threadIdx.x & 31, wid = threadIdx.x >> 5;
#pragma unroll
    for (int o = 16; o; o >>= 1) v += __shfl_xor_sync(0xffffffffu, v, o);
    if (lane == 0) sh[wid] = v;
    __syncthreads();
    float r = 0.f;
#pragma unroll
    for (int i = 0; i < 8; i++) r += sh[i];
    __syncthreads();
    return r;
}

__device__ __forceinline__ float blockReduceMax(float v) {
    __shared__ float sh[8];
    int lane = threadIdx.x & 31, wid = threadIdx.x >> 5;
#pragma unroll
    for (int o = 16; o; o >>= 1) v = fmaxf(v, __shfl_xor_sync(0xffffffffu, v, o));
    if (lane == 0) sh[wid] = v;
    __syncthreads();
    float r = -3.402823466e38f;
#pragma unroll
    for (int i = 0; i < 8; i++) r = fmaxf(r, sh[i]);
    __syncthreads();
    return r;
}

// ---------------- prep: fold BN into conv weights ----------------
__global__ void prep_kernel(
    const float* __restrict__ Wk, const float* __restrict__ kg, const float* __restrict__ kb,
    const float* __restrict__ km, const float* __restrict__ kvv,
    const float* __restrict__ Wq, const float* __restrict__ qg, const float* __restrict__ qb,
    const float* __restrict__ qm, const float* __restrict__ qv,
    const float* __restrict__ Wv, const float* __restrict__ vg, const float* __restrict__ vb,
    const float* __restrict__ vm, const float* __restrict__ vv)
{
    int o = blockIdx.x, m = blockIdx.y, i = threadIdx.x;
    const float *W, *ga, *be, *me, *va;
    if (m == 0)      { W = Wq; ga = qg; be = qb; me = qm; va = qv; }
    else if (m == 1) { W = Wk; ga = kg; be = kb; me = km; va = kvv; }
    else             { W = Wv; ga = vg; be = vb; me = vm; va = vv; }
    float inv = ga[o] / sqrtf(va[o] + EPSV);
    float a = inv * W[o*CC + i];
    if (m == 0)      { g_Aq[o*CC + i] = a;  if (i == 0) g_bq[o] = be[o] - me[o]*inv; }
    else if (m == 1) { g_Ak[o*CC + i] = a;  if (i == 0) g_bk[o] = be[o] - me[o]*inv; }
    else             { g_AvT[i*CC + o] = a; if (i == 0) g_bv[o] = be[o] - me[o]*inv; }
}

// ---------------- row sums s[n][c] = sum_s X ----------------
__global__ void rowsum_kernel(const float* __restrict__ x) {
    int c = blockIdx.x, n = blockIdx.y, t = threadIdx.x;
    const float4* xr = (const float4*)(x + ((size_t)n*CC + c)*SS);
    float acc = 0.f;
    for (int i = t; i < SS/4; i += 256) {
        float4 v = xr[i];
        acc += (v.x + v.y) + (v.z + v.w);
    }
    float tot = blockReduceSum(acc);
    if (t == 0) g_s[n*CC + c] = tot;
}

// ---------------- G = X X^T  (64x64 tiles, full-S reduction per CTA) ----------------
__global__ void __launch_bounds__(256) gram_kernel(const float* __restrict__ x) {
    __shared__ float Xis[16*64];
    __shared__ float Xjs[16*64];
    int bj = blockIdx.x, bi = blockIdx.y, n = blockIdx.z;
    int tid = threadIdx.x, tx = tid & 15, ty = tid >> 4;
    int lrow = tid >> 2, lc4 = tid & 3;

    const float* xi = x + ((size_t)n*CC + bi*64 + lrow)*SS + lc4*4;
    const float* xj = x + ((size_t)n*CC + bj*64 + lrow)*SS + lc4*4;

    float acc[4][4] = {};
    float4 a = *(const float4*)xi;
    float4 b = *(const float4*)xj;

    for (int kc = 0; kc < SS; kc += 16) {
        Xis[(lc4*4+0)*64 + lrow] = a.x;
        Xis[(lc4*4+1)*64 + lrow] = a.y;
        Xis[(lc4*4+2)*64 + lrow] = a.z;
        Xis[(lc4*4+3)*64 + lrow] = a.w;
        Xjs[(lc4*4+0)*64 + lrow] = b.x;
        Xjs[(lc4*4+1)*64 + lrow] = b.y;
        Xjs[(lc4*4+2)*64 + lrow] = b.z;
        Xjs[(lc4*4+3)*64 + lrow] = b.w;
        __syncthreads();
        int kn = (kc + 16 < SS) ? kc + 16 : kc;   // prefetch next chunk (redundant on last)
        a = *(const float4*)(xi + kn);
        b = *(const float4*)(xj + kn);
#pragma unroll
        for (int kk = 0; kk < 16; kk++) {
            float4 av = *(const float4*)&Xis[kk*64 + ty*4];
            float4 bv = *(const float4*)&Xjs[kk*64 + tx*4];
            acc[0][0] += av.x*bv.x; acc[0][1] += av.x*bv.y; acc[0][2] += av.x*bv.z; acc[0][3] += av.x*bv.w;
            acc[1][0] += av.y*bv.x; acc[1][1] += av.y*bv.y; acc[1][2] += av.y*bv.z; acc[1][3] += av.y*bv.w;
            acc[2][0] += av.z*bv.x; acc[2][1] += av.z*bv.y; acc[2][2] += av.z*bv.z; acc[2][3] += av.z*bv.w;
            acc[3][0] += av.w*bv.x; acc[3][1] += av.w*bv.y; acc[3][2] += av.w*bv.z; acc[3][3] += av.w*bv.w;
        }
        __syncthreads();
    }

    float* out = g_G + ((size_t)n*CC + bi*64 + ty*4)*CC + bj*64 + tx*4;
#pragma unroll
    for (int u = 0; u < 4; u++) {
        float4 o = make_float4(acc[u][0], acc[u][1], acc[u][2], acc[u][3]);
        *(float4*)(out + (size_t)u*CC) = o;
    }
}

// ---------------- batched 256x256x256 NT GEMM (mode-dispatched) ----------------
// mode 0: P = Aq @ G_n          (G symmetric -> NT ok)
// mode 1: L = P_n @ Ak^T + u[c]*bk[d] + bq[c]*(w[d] + S*bk[d])
// mode 2: M = attn_n @ Av + I   (via AvT, NT form)
__global__ void __launch_bounds__(256) gemm256_nt_kernel(int mode) {
    __shared__ float As[16*64];
    __shared__ float Bs[16*64];
    int bj = blockIdx.x, bi = blockIdx.y, n = blockIdx.z;
    int tid = threadIdx.x, tx = tid & 15, ty = tid >> 4;
    int lrow = tid >> 2, lc4 = tid & 3;

    const float* A; const float* Bm; float* Out;
    if (mode == 0)      { A = g_Aq;                    Bm = g_G + (size_t)n*CC*CC; Out = g_P + (size_t)n*CC*CC; }
    else if (mode == 1) { A = g_P + (size_t)n*CC*CC;   Bm = g_Ak;                  Out = g_L + (size_t)n*CC*CC; }
    else                { A = g_L + (size_t)n*CC*CC;   Bm = g_AvT;                 Out = g_M + (size_t)n*CC*CC; }

    const float* ap = A  + (size_t)(bi*64 + lrow)*CC + lc4*4;
    const float* bp = Bm + (size_t)(bj*64 + lrow)*CC + lc4*4;

    float acc[4][4] = {};
    float4 a = *(const float4*)ap;
    float4 b = *(const float4*)bp;

    for (int kc = 0; kc < CC; kc += 16) {
        As[(lc4*4+0)*64 + lrow] = a.x;
        As[(lc4*4+1)*64 + lrow] = a.y;
        As[(lc4*4+2)*64 + lrow] = a.z;
        As[(lc4*4+3)*64 + lrow] = a.w;
        Bs[(lc4*4+0)*64 + lrow] = b.x;
        Bs[(lc4*4+1)*64 + lrow] = b.y;
        Bs[(lc4*4+2)*64 + lrow] = b.z;
        Bs[(lc4*4+3)*64 + lrow] = b.w;
        __syncthreads();
        int kn = (kc + 16 < CC) ? kc + 16 : kc;
        a = *(const float4*)(ap + kn);
        b = *(const float4*)(bp + kn);
#pragma unroll
        for (int kk = 0; kk < 16; kk++) {
            float4 av = *(const float4*)&As[kk*64 + ty*4];
            float4 bv = *(const float4*)&Bs[kk*64 + tx*4];
            acc[0][0] += av.x*bv.x; acc[0][1] += av.x*bv.y; acc[0][2] += av.x*bv.z; acc[0][3] += av.x*bv.w;
            acc[1][0] += av.y*bv.x; acc[1][1] += av.y*bv.y; acc[1][2] += av.y*bv.z; acc[1][3] += av.y*bv.w;
            acc[2][0] += av.z*bv.x; acc[2][1] += av.z*bv.y; acc[2][2] += av.z*bv.z; acc[2][3] += av.z*bv.w;
            acc[3][0] += av.w*bv.x; acc[3][1] += av.w*bv.y; acc[3][2] += av.w*bv.z; acc[3][3] += av.w*bv.w;
        }
        __syncthreads();
    }

    int row = bi*64 + ty*4;
    int col = bj*64 + tx*4;
    if (mode == 1) {
#pragma unroll
        for (int u = 0; u < 4; u++) {
            float uu = g_u[n*CC + row + u];
            float bb = g_bq[row + u];
#pragma unroll
            for (int v = 0; v < 4; v++) {
                float bk = g_bk[col + v];
                acc[u][v] += uu*bk + bb*(g_w[n*CC + col + v] + (float)SS*bk);
            }
        }
    } else if (mode == 2) {
#pragma unroll
        for (int u = 0; u < 4; u++)
#pragma unroll
            for (int v = 0; v < 4; v++)
                if (row + u == col + v) acc[u][v] += 1.0f;
    }

    float* out = Out + (size_t)row*CC + col;
#pragma unroll
    for (int u = 0; u < 4; u++) {
        float4 o = make_float4(acc[u][0], acc[u][1], acc[u][2], acc[u][3]);
        *(float4*)(out + (size_t)u*CC) = o;
    }
}

// ---------------- small matvecs ----------------
// mode 0: u = Aq @ s_n ; mode 1: w = Ak @ s_n ; mode 2: c = attn_n @ bv
__global__ void matvec_kernel(int mode) {
    int r = blockIdx.x, n = blockIdx.y, t = threadIdx.x;
    const float* Arow; const float* vec; float* out;
    if (mode == 0)      { Arow = g_Aq + (size_t)r*CC;                 vec = g_s + n*CC; out = g_u  + n*CC + r; }
    else if (mode == 1) { Arow = g_Ak + (size_t)r*CC;                 vec = g_s + n*CC; out = g_w  + n*CC + r; }
    else                { Arow = g_L + ((size_t)n*CC + r)*CC;         vec = g_bv;       out = g_cv + n*CC + r; }
    float p = Arow[t] * vec[t];
    float tot = blockReduceSum(p);
    if (t == 0) *out = tot;
}

// ---------------- row softmax over C=256 (in place on g_L) ----------------
__global__ void softmax_kernel() {
    int r = blockIdx.x, n = blockIdx.y, t = threadIdx.x;
    float* row = g_L + ((size_t)n*CC + r)*CC;
    float v = row[t];
    float m = blockReduceMax(v);
    float e = expf(v - m);
    float ss = blockReduceSum(e);
    row[t] = e / ss;
}

// ---------------- out = (M+I) @ X + c  (64 c-rows x 128 s-cols tiles) ----------------
__global__ void __launch_bounds__(256) out_kernel(const float* __restrict__ x, float* __restrict__ out) {
    __shared__ float As[16*64];
    __shared__ float Bs[16*128];
    int bs = blockIdx.x, bc = blockIdx.y, n = blockIdx.z;
    int tid = threadIdx.x, tx = tid & 15, ty = tid >> 4;
    int arow = tid >> 2, ac4 = tid & 3;

    const float* Ap = g_M + ((size_t)n*CC + bc*64 + arow)*CC + ac4*4;
    const float* Xb = x + (size_t)n*CC*SS + (size_t)bs*128;

    float acc[4][8] = {};

    float4 a  = *(const float4*)Ap;
    float4 b0, b1;
    {
        int s0 = tid,        r0 = s0 >> 5, c0 = s0 & 31;
        int s1 = tid + 256,  r1 = s1 >> 5, c1 = s1 & 31;
        b0 = *(const float4*)(Xb + (size_t)r0*SS + c0*4);
        b1 = *(const float4*)(Xb + (size_t)r1*SS + c1*4);
    }

    for (int kc = 0; kc < CC; kc += 16) {
        As[(ac4*4+0)*64 + arow] = a.x;
        As[(ac4*4+1)*64 + arow] = a.y;
        As[(ac4*4+2)*64 + arow] = a.z;
        As[(ac4*4+3)*64 + arow] = a.w;
        {
            int s0 = tid,       r0 = s0 >> 5, c0 = s0 & 31;
            int s1 = tid + 256, r1 = s1 >> 5, c1 = s1 & 31;
            *(float4*)&Bs[r0*128 + c0*4] = b0;
            *(float4*)&Bs[r1*128 + c1*4] = b1;
        }
        __syncthreads();
        int kn = (kc + 16 < CC) ? kc + 16 : kc;
        a = *(const float4*)(Ap + kn);
        {
            int s0 = tid,       r0 = s0 >> 5, c0 = s0 & 31;
            int s1 = tid + 256, r1 = s1 >> 5, c1 = s1 & 31;
            b0 = *(const float4*)(Xb + (size_t)(kn + r0)*SS + c0*4);
            b1 = *(const float4*)(Xb + (size_t)(kn + r1)*SS + c1*4);
        }
#pragma unroll
        for (int kk = 0; kk < 16; kk++) {
            float4 av = *(const float4*)&As[kk*64 + ty*4];
            float4 p0 = *(const float4*)&Bs[kk*128 + tx*8];
            float4 p1 = *(const float4*)&Bs[kk*128 + tx*8 + 4];
            float am[4] = {av.x, av.y, av.z, av.w};
#pragma unroll
            for (int u = 0; u < 4; u++) {
                acc[u][0] += am[u]*p0.x; acc[u][1] += am[u]*p0.y;
                acc[u][2] += am[u]*p0.z; acc[u][3] += am[u]*p0.w;
                acc[u][4] += am[u]*p1.x; acc[u][5] += am[u]*p1.y;
                acc[u][6] += am[u]*p1.z; acc[u][7] += am[u]*p1.w;
            }
        }
        __syncthreads();
    }

#pragma unroll
    for (int u = 0; u < 4; u++) {
        int c = bc*64 + ty*4 + u;
        float cv = g_cv[n*CC + c];
        float* op = out + ((size_t)n*CC + c)*SS + (size_t)bs*128 + tx*8;
        float4 o0 = make_float4(acc[u][0] + cv, acc[u][1] + cv, acc[u][2] + cv, acc[u][3] + cv);
        float4 o1 = make_float4(acc[u][4] + cv, acc[u][5] + cv, acc[u][6] + cv, acc[u][7] + cv);
        *(float4*)op       = o0;
        *(float4*)(op + 4) = o1;
    }
}

// ---------------- launcher ----------------
extern "C" void kernel_launch(void* const* d_in, const int* in_sizes, int n_in,
                              void* d_out, int out_size) {
    const float* x   = (const float*)d_in[0];
    const float* Wk  = (const float*)d_in[1];
    const float* kg  = (const float*)d_in[2];
    const float* kb  = (const float*)d_in[3];
    const float* km  = (const float*)d_in[4];
    const float* kv  = (const float*)d_in[5];
    const float* Wq  = (const float*)d_in[6];
    const float* qg  = (const float*)d_in[7];
    const float* qb  = (const float*)d_in[8];
    const float* qm  = (const float*)d_in[9];
    const float* qv  = (const float*)d_in[10];
    const float* Wv  = (const float*)d_in[11];
    const float* vg  = (const float*)d_in[12];
    const float* vb  = (const float*)d_in[13];
    const float* vm  = (const float*)d_in[14];
    const float* vv  = (const float*)d_in[15];
    float* out = (float*)d_out;

    prep_kernel<<<dim3(CC, 3), CC>>>(Wk, kg, kb, km, kv, Wq, qg, qb, qm, qv, Wv, vg, vb, vm, vv);
    rowsum_kernel<<<dim3(CC, BB), 256>>>(x);
    gram_kernel<<<dim3(4, 4, BB), 256>>>(x);
    gemm256_nt_kernel<<<dim3(4, 4, BB), 256>>>(0);   // P = Aq @ G
    matvec_kernel<<<dim3(CC, BB), 256>>>(0);         // u = Aq @ s
    matvec_kernel<<<dim3(CC, BB), 256>>>(1);         // w = Ak @ s
    gemm256_nt_kernel<<<dim3(4, 4, BB), 256>>>(1);   // L = P @ Ak^T + rank-1 terms
    softmax_kernel<<<dim3(CC, BB), 256>>>();
    gemm256_nt_kernel<<<dim3(4, 4, BB), 256>>>(2);   // M = attn @ Av + I
    matvec_kernel<<<dim3(CC, BB), 256>>>(2);         // c = attn @ bv
    out_kernel<<<dim3(SS/128, CC/64, BB), 256>>>(x, out);
}

// round 5
// speedup vs baseline: 1.1174x; 1.1174x over previous
#include <cuda_runtime.h>
#include <math.h>
#include <stdint.h>
#include <mma.h>

using namespace nvcuda;

#define BB 8
#define CC 256
#define SS 16384
#define EPSV 1e-5f
#define KSPLIT 16

// ---------------- scratch ----------------
__device__ float g_Gp[(size_t)KSPLIT*BB*CC*CC];
__device__ float g_G [BB*CC*CC];
__device__ float g_P [BB*CC*CC];
__device__ float g_L [BB*CC*CC];
__device__ float g_M [BB*CC*CC];
__device__ float g_Aq[CC*CC];
__device__ float g_Ak[CC*CC];
__device__ float g_AvT[CC*CC];
__device__ float g_bq[CC];
__device__ float g_bk[CC];
__device__ float g_bv[CC];
__device__ float g_s [BB*CC];
__device__ float g_u [BB*CC];
__device__ float g_w [BB*CC];
__device__ float g_cv[BB*CC];

// ---------------- 3xTF32 fragment split ----------------
template <typename Frag>
__device__ __forceinline__ void split_tf32(const Frag& f, Frag& hi, Frag& lo) {
#pragma unroll
    for (int e = 0; e < f.num_elements; e++) {
        float v = f.x[e];
        float h = wmma::__float_to_tf32(v);
        hi.x[e] = h;
        lo.x[e] = wmma::__float_to_tf32(v - h);
    }
}

// ---------------- reductions ----------------
__device__ __forceinline__ float blockReduceSum(float v) {
    __shared__ float sh[8];
    int lane = threadIdx.x & 31, wid = threadIdx.x >> 5;
#pragma unroll
    for (int o = 16; o; o >>= 1) v += __shfl_xor_sync(0xffffffffu, v, o);
    if (lane == 0) sh[wid] = v;
    __syncthreads();
    float r = 0.f;
#pragma unroll
    for (int i = 0; i < 8; i++) r += sh[i];
    __syncthreads();
    return r;
}
__device__ __forceinline__ float blockReduceMax(float v) {
    __shared__ float sh[8];
    int lane = threadIdx.x & 31, wid = threadIdx.x >> 5;
#pragma unroll
    for (int o = 16; o; o >>= 1) v = fmaxf(v, __shfl_xor_sync(0xffffffffu, v, o));
    if (lane == 0) sh[wid] = v;
    __syncthreads();
    float r = -3.402823466e38f;
#pragma unroll
    for (int i = 0; i < 8; i++) r = fmaxf(r, sh[i]);
    __syncthreads();
    return r;
}

// ---------------- prep: fold BN into conv weights ----------------
__global__ void prep_kernel(
    const float* __restrict__ Wk, const float* __restrict__ kg, const float* __restrict__ kb,
    const float* __restrict__ km, const float* __restrict__ kvv,
    const float* __restrict__ Wq, const float* __restrict__ qg, const float* __restrict__ qb,
    const float* __restrict__ qm, const float* __restrict__ qv,
    const float* __restrict__ Wv, const float* __restrict__ vg, const float* __restrict__ vb,
    const float* __restrict__ vm, const float* __restrict__ vv)
{
    int o = blockIdx.x, m = blockIdx.y, i = threadIdx.x;
    const float *W, *ga, *be, *me, *va;
    if (m == 0)      { W = Wq; ga = qg; be = qb; me = qm; va = qv; }
    else if (m == 1) { W = Wk; ga = kg; be = kb; me = km; va = kvv; }
    else             { W = Wv; ga = vg; be = vb; me = vm; va = vv; }
    float inv = ga[o] / sqrtf(va[o] + EPSV);
    float a = inv * W[o*CC + i];
    if (m == 0)      { g_Aq[o*CC + i] = a;  if (i == 0) g_bq[o] = be[o] - me[o]*inv; }
    else if (m == 1) { g_Ak[o*CC + i] = a;  if (i == 0) g_bk[o] = be[o] - me[o]*inv; }
    else             { g_AvT[i*CC + o] = a; if (i == 0) g_bv[o] = be[o] - me[o]*inv; }
}

// ---------------- rowsum ----------------
__global__ void rowsum_kernel(const float* __restrict__ x) {
    int c = blockIdx.x, n = blockIdx.y, t = threadIdx.x;
    const float4* xr = (const float4*)(x + ((size_t)n*CC + c)*SS);
    float acc = 0.f;
    for (int i = t; i < SS/4; i += 256) {
        float4 v = xr[i];
        acc += (v.x + v.y) + (v.z + v.w);
    }
    float tot = blockReduceSum(acc);
    if (t == 0) g_s[n*CC + c] = tot;
}

// ---------------- gram partials via 3xTF32 WMMA ----------------
#define GPAD 4
#define GLD (32 + GPAD)
__global__ void __launch_bounds__(256) gram_wmma_kernel(const float* __restrict__ x) {
    __shared__ float As[128*GLD];
    __shared__ float Bs[128*GLD];
    const int tid = threadIdx.x, w = tid >> 5;
    const int wm = w >> 1, wn = w & 1;          // warp grid 4x2 -> 32x64 warp tiles
    const int bi = blockIdx.x >> 1, bj = blockIdx.x & 1;
    const int zk = blockIdx.y, n = blockIdx.z;
    const int s0 = zk * (SS / KSPLIT);

    const int row = tid >> 1, part = tid & 1;
    const float* xa = x + ((size_t)n*CC + bi*128 + row)*SS + s0 + part*16;
    const float* xb = x + ((size_t)n*CC + bj*128 + row)*SS + s0 + part*16;

    wmma::fragment<wmma::accumulator, 16, 16, 8, float> acc[2][4];
#pragma unroll
    for (int i = 0; i < 2; i++)
#pragma unroll
        for (int j = 0; j < 4; j++) wmma::fill_fragment(acc[i][j], 0.0f);

    for (int t = 0; t < SS/KSPLIT; t += 32) {
#pragma unroll
        for (int q = 0; q < 4; q++) {
            *(float4*)&As[row*GLD + part*16 + q*4] = *(const float4*)(xa + t + q*4);
            *(float4*)&Bs[row*GLD + part*16 + q*4] = *(const float4*)(xb + t + q*4);
        }
        __syncthreads();
#pragma unroll
        for (int ks = 0; ks < 4; ks++) {
            wmma::fragment<wmma::matrix_a, 16, 16, 8, wmma::precision::tf32, wmma::row_major> ah[2], al[2];
            wmma::fragment<wmma::matrix_b, 16, 16, 8, wmma::precision::tf32, wmma::col_major> bh[4], bl[4];
#pragma unroll
            for (int i = 0; i < 2; i++) {
                wmma::fragment<wmma::matrix_a, 16, 16, 8, wmma::precision::tf32, wmma::row_major> raw;
                wmma::load_matrix_sync(raw, &As[(wm*32 + i*16)*GLD + ks*8], GLD);
                split_tf32(raw, ah[i], al[i]);
            }
#pragma unroll
            for (int j = 0; j < 4; j++) {
                wmma::fragment<wmma::matrix_b, 16, 16, 8, wmma::precision::tf32, wmma::col_major> raw;
                wmma::load_matrix_sync(raw, &Bs[(wn*64 + j*16)*GLD + ks*8], GLD);
                split_tf32(raw, bh[j], bl[j]);
            }
#pragma unroll
            for (int i = 0; i < 2; i++)
#pragma unroll
                for (int j = 0; j < 4; j++) {
                    wmma::mma_sync(acc[i][j], ah[i], bl[j], acc[i][j]);
                    wmma::mma_sync(acc[i][j], al[i], bh[j], acc[i][j]);
                    wmma::mma_sync(acc[i][j], ah[i], bh[j], acc[i][j]);
                }
        }
        __syncthreads();
    }

    float* gp = g_Gp + ((size_t)zk*BB + n)*CC*CC;
#pragma unroll
    for (int i = 0; i < 2; i++)
#pragma unroll
        for (int j = 0; j < 4; j++)
            wmma::store_matrix_sync(
                gp + (size_t)(bi*128 + wm*32 + i*16)*CC + bj*128 + wn*64 + j*16,
                acc[i][j], CC, wmma::mem_row_major);
}

// ---------------- reduce gram partials ----------------
__global__ void reduceG_kernel() {
    size_t i = (size_t)blockIdx.x*256 + threadIdx.x;
    float s = 0.f;
#pragma unroll
    for (int z = 0; z < KSPLIT; z++) s += g_Gp[(size_t)z*(BB*CC*CC) + i];
    g_G[i] = s;
}

// ---------------- middle chain: 256^3 NT GEMM (SIMT fp32) ----------------
__global__ void __launch_bounds__(256) gemm256_nt_kernel(int mode) {
    __shared__ float As[16*64];
    __shared__ float Bs[16*64];
    int bj = blockIdx.x, bi = blockIdx.y, n = blockIdx.z;
    int tid = threadIdx.x, tx = tid & 15, ty = tid >> 4;
    int lrow = tid >> 2, lc4 = tid & 3;

    const float* A; const float* Bm; float* Out;
    if (mode == 0)      { A = g_Aq;                  Bm = g_G + (size_t)n*CC*CC; Out = g_P + (size_t)n*CC*CC; }
    else if (mode == 1) { A = g_P + (size_t)n*CC*CC; Bm = g_Ak;                  Out = g_L + (size_t)n*CC*CC; }
    else                { A = g_L + (size_t)n*CC*CC; Bm = g_AvT;                 Out = g_M + (size_t)n*CC*CC; }

    const float* ap = A  + (size_t)(bi*64 + lrow)*CC + lc4*4;
    const float* bp = Bm + (size_t)(bj*64 + lrow)*CC + lc4*4;

    float acc[4][4] = {};
    float4 a = *(const float4*)ap;
    float4 b = *(const float4*)bp;

    for (int kc = 0; kc < CC; kc += 16) {
        As[(lc4*4+0)*64 + lrow] = a.x;  As[(lc4*4+1)*64 + lrow] = a.y;
        As[(lc4*4+2)*64 + lrow] = a.z;  As[(lc4*4+3)*64 + lrow] = a.w;
        Bs[(lc4*4+0)*64 + lrow] = b.x;  Bs[(lc4*4+1)*64 + lrow] = b.y;
        Bs[(lc4*4+2)*64 + lrow] = b.z;  Bs[(lc4*4+3)*64 + lrow] = b.w;
        __syncthreads();
        int kn = (kc + 16 < CC) ? kc + 16 : kc;
        a = *(const float4*)(ap + kn);
        b = *(const float4*)(bp + kn);
#pragma unroll
        for (int kk = 0; kk < 16; kk++) {
            float4 av = *(const float4*)&As[kk*64 + ty*4];
            float4 bv = *(const float4*)&Bs[kk*64 + tx*4];
            acc[0][0] += av.x*bv.x; acc[0][1] += av.x*bv.y; acc[0][2] += av.x*bv.z; acc[0][3] += av.x*bv.w;
            acc[1][0] += av.y*bv.x; acc[1][1] += av.y*bv.y; acc[1][2] += av.y*bv.z; acc[1][3] += av.y*bv.w;
            acc[2][0] += av.z*bv.x; acc[2][1] += av.z*bv.y; acc[2][2] += av.z*bv.z; acc[2][3] += av.z*bv.w;
            acc[3][0] += av.w*bv.x; acc[3][1] += av.w*bv.y; acc[3][2] += av.w*bv.z; acc[3][3] += av.w*bv.w;
        }
        __syncthreads();
    }

    int row = bi*64 + ty*4, col = bj*64 + tx*4;
    if (mode == 1) {
#pragma unroll
        for (int u = 0; u < 4; u++) {
            float uu = g_u[n*CC + row + u], bb = g_bq[row + u];
#pragma unroll
            for (int v = 0; v < 4; v++) {
                float bk = g_bk[col + v];
                acc[u][v] += uu*bk + bb*(g_w[n*CC + col + v] + (float)SS*bk);
            }
        }
    } else if (mode == 2) {
#pragma unroll
        for (int u = 0; u < 4; u++)
#pragma unroll
            for (int v = 0; v < 4; v++)
                if (row + u == col + v) acc[u][v] += 1.0f;
    }

    float* out = Out + (size_t)row*CC + col;
#pragma unroll
    for (int u = 0; u < 4; u++)
        *(float4*)(out + (size_t)u*CC) = make_float4(acc[u][0], acc[u][1], acc[u][2], acc[u][3]);
}

// ---------------- matvecs ----------------
__global__ void matvec_kernel(int mode) {
    int r = blockIdx.x, n = blockIdx.y, t = threadIdx.x;
    const float* Arow; const float* vec; float* out;
    if (mode == 0)      { Arow = g_Aq + (size_t)r*CC;         vec = g_s + n*CC; out = g_u  + n*CC + r; }
    else if (mode == 1) { Arow = g_Ak + (size_t)r*CC;         vec = g_s + n*CC; out = g_w  + n*CC + r; }
    else                { Arow = g_L + ((size_t)n*CC + r)*CC; vec = g_bv;       out = g_cv + n*CC + r; }
    float p = Arow[t] * vec[t];
    float tot = blockReduceSum(p);
    if (t == 0) *out = tot;
}

// ---------------- softmax ----------------
__global__ void softmax_kernel() {
    int r = blockIdx.x, n = blockIdx.y, t = threadIdx.x;
    float* row = g_L + ((size_t)n*CC + r)*CC;
    float v = row[t];
    float m = blockReduceMax(v);
    float e = expf(v - m);
    float ss = blockReduceSum(e);
    row[t] = e / ss;
}

// ---------------- out = (M+I) @ X + c via 3xTF32 WMMA ----------------
#define OLDA (32 + 4)
#define OLDB (128 + 4)
#define OUT_SMEM (128*OLDB*4)
__global__ void __launch_bounds__(256) out_wmma_kernel(const float* __restrict__ x,
                                                       float* __restrict__ out) {
    extern __shared__ float sm[];
    float* As = sm;                 // 128 x OLDA
    float* Bs = sm + 128*OLDA;      // 32 x OLDB
    float* Cs = sm;                 // 128 x OLDB (after loop)

    const int tid = threadIdx.x, w = tid >> 5;
    const int wm = w >> 1, wn = w & 1;
    const int bs = blockIdx.x, bc = blockIdx.y, n = blockIdx.z;
    const int s0 = bs*128, c0 = bc*128;

    const float* Mfb = g_M + (size_t)n*CC*CC;
    const float* Xb  = x + (size_t)n*CC*SS;

    wmma::fragment<wmma::accumulator, 16, 16, 8, float> acc[2][4];
#pragma unroll
    for (int i = 0; i < 2; i++)
#pragma unroll
        for (int j = 0; j < 4; j++) wmma::fill_fragment(acc[i][j], 0.0f);

    const int arow = tid >> 1, apart = tid & 1;

    for (int kb = 0; kb < CC; kb += 32) {
#pragma unroll
        for (int q = 0; q < 4; q++)
            *(float4*)&As[arow*OLDA + apart*16 + q*4] =
                *(const float4*)(Mfb + (size_t)(c0 + arow)*CC + kb + apart*16 + q*4);
#pragma unroll
        for (int i = 0; i < 4; i++) {
            int idx = i*256 + tid;
            int r = idx >> 5, c4 = idx & 31;
            *(float4*)&Bs[r*OLDB + c4*4] =
                *(const float4*)(Xb + (size_t)(kb + r)*SS + s0 + c4*4);
        }
        __syncthreads();
#pragma unroll
        for (int ks = 0; ks < 4; ks++) {
            wmma::fragment<wmma::matrix_a, 16, 16, 8, wmma::precision::tf32, wmma::row_major> ah[2], al[2];
            wmma::fragment<wmma::matrix_b, 16, 16, 8, wmma::precision::tf32, wmma::row_major> bh[4], bl[4];
#pragma unroll
            for (int i = 0; i < 2; i++) {
                wmma::fragment<wmma::matrix_a, 16, 16, 8, wmma::precision::tf32, wmma::row_major> raw;
                wmma::load_matrix_sync(raw, &As[(wm*32 + i*16)*OLDA + ks*8], OLDA);
                split_tf32(raw, ah[i], al[i]);
            }
#pragma unroll
            for (int j = 0; j < 4; j++) {
                wmma::fragment<wmma::matrix_b, 16, 16, 8, wmma::precision::tf32, wmma::row_major> raw;
                wmma::load_matrix_sync(raw, &Bs[(ks*8)*OLDB + wn*64 + j*16], OLDB);
                split_tf32(raw, bh[j], bl[j]);
            }
#pragma unroll
            for (int i = 0; i < 2; i++)
#pragma unroll
                for (int j = 0; j < 4; j++) {
                    wmma::mma_sync(acc[i][j], ah[i], bl[j], acc[i][j]);
                    wmma::mma_sync(acc[i][j], al[i], bh[j], acc[i][j]);
                    wmma::mma_sync(acc[i][j], ah[i], bh[j], acc[i][j]);
                }
        }
        __syncthreads();
    }

    // epilogue: stage C in smem, add cv[c], write coalesced
#pragma unroll
    for (int i = 0; i < 2; i++)
#pragma unroll
        for (int j = 0; j < 4; j++)
            wmma::store_matrix_sync(&Cs[(wm*32 + i*16)*OLDB + wn*64 + j*16],
                                    acc[i][j], OLDB, wmma::mem_row_major);
    __syncthreads();

    const int crow = tid >> 1, cpart = tid & 1;
    float cv = g_cv[n*CC + c0 + crow];
    float* op = out + ((size_t)n*CC + c0 + crow)*SS + s0 + cpart*64;
#pragma unroll
    for (int q = 0; q < 16; q++) {
        float4 v = *(float4*)&Cs[crow*OLDB + cpart*64 + q*4];
        v.x += cv; v.y += cv; v.z += cv; v.w += cv;
        *(float4*)(op + q*4) = v;
    }
}

// ---------------- launcher ----------------
extern "C" void kernel_launch(void* const* d_in, const int* in_sizes, int n_in,
                              void* d_out, int out_size) {
    const float* x   = (const float*)d_in[0];
    const float* Wk  = (const float*)d_in[1];
    const float* kg  = (const float*)d_in[2];
    const float* kb  = (const float*)d_in[3];
    const float* km  = (const float*)d_in[4];
    const float* kv  = (const float*)d_in[5];
    const float* Wq  = (const float*)d_in[6];
    const float* qg  = (const float*)d_in[7];
    const float* qb  = (const float*)d_in[8];
    const float* qm  = (const float*)d_in[9];
    const float* qv  = (const float*)d_in[10];
    const float* Wv  = (const float*)d_in[11];
    const float* vg  = (const float*)d_in[12];
    const float* vb  = (const float*)d_in[13];
    const float* vm  = (const float*)d_in[14];
    const float* vv  = (const float*)d_in[15];
    float* out = (float*)d_out;

    cudaFuncSetAttribute(out_wmma_kernel, cudaFuncAttributeMaxDynamicSharedMemorySize, OUT_SMEM);

    prep_kernel<<<dim3(CC, 3), CC>>>(Wk, kg, kb, km, kv, Wq, qg, qb, qm, qv, Wv, vg, vb, vm, vv);
    rowsum_kernel<<<dim3(CC, BB), 256>>>(x);
    gram_wmma_kernel<<<dim3(4, KSPLIT, BB), 256>>>(x);
    reduceG_kernel<<<BB*CC*CC/256, 256>>>();
    gemm256_nt_kernel<<<dim3(4, 4, BB), 256>>>(0);   // P = Aq @ G
    matvec_kernel<<<dim3(CC, BB), 256>>>(0);         // u = Aq @ s
    matvec_kernel<<<dim3(CC, BB), 256>>>(1);         // w = Ak @ s
    gemm256_nt_kernel<<<dim3(4, 4, BB), 256>>>(1);   // L = P @ Ak^T + rank-1
    softmax_kernel<<<dim3(CC, BB), 256>>>();
    gemm256_nt_kernel<<<dim3(4, 4, BB), 256>>>(2);   // M = attn @ Av + I
    matvec_kernel<<<dim3(CC, BB), 256>>>(2);         // c = attn @ bv
    out_wmma_kernel<<<dim3(SS/128, CC/128, BB), 256, OUT_SMEM>>>(x, out);
}

// round 7
// speedup vs baseline: 1.2533x; 1.1217x over previous
#include <cuda_runtime.h>
#include <math.h>
#include <stdint.h>
#include <mma.h>

using namespace nvcuda;

#define BB 8
#define CC 256
#define SS 16384
#define EPSV 1e-5f
#define KSPLIT 16

// ---------------- scratch ----------------
__device__ float g_Gp[(size_t)KSPLIT*BB*CC*CC];
__device__ float g_G [BB*CC*CC];
__device__ float g_P [BB*CC*CC];
__device__ float g_L [BB*CC*CC];
__device__ float g_M [BB*CC*CC];
__device__ float g_Aq[CC*CC];
__device__ float g_Ak[CC*CC];
__device__ float g_AvT[CC*CC];
__device__ float g_bq[CC];
__device__ float g_bk[CC];
__device__ float g_bv[CC];
__device__ float g_s [BB*CC];
__device__ float g_u [BB*CC];
__device__ float g_w [BB*CC];
__device__ float g_cv[BB*CC];

// ---------------- split helper (staging-time) ----------------
__device__ __forceinline__ void split2(float v, float& h, float& l) {
    h = wmma::__float_to_tf32(v);
    l = wmma::__float_to_tf32(v - h);
}

// ---------------- reductions ----------------
__device__ __forceinline__ float blockReduceSum(float v) {
    __shared__ float sh[8];
    int lane = threadIdx.x & 31, wid = threadIdx.x >> 5;
#pragma unroll
    for (int o = 16; o; o >>= 1) v += __shfl_xor_sync(0xffffffffu, v, o);
    if (lane == 0) sh[wid] = v;
    __syncthreads();
    float r = 0.f;
#pragma unroll
    for (int i = 0; i < 8; i++) r += sh[i];
    __syncthreads();
    return r;
}
__device__ __forceinline__ float blockReduceMax(float v) {
    __shared__ float sh[8];
    int lane = threadIdx.x & 31, wid = threadIdx.x >> 5;
#pragma unroll
    for (int o = 16; o; o >>= 1) v = fmaxf(v, __shfl_xor_sync(0xffffffffu, v, o));
    if (lane == 0) sh[wid] = v;
    __syncthreads();
    float r = -3.402823466e38f;
#pragma unroll
    for (int i = 0; i < 8; i++) r = fmaxf(r, sh[i]);
    __syncthreads();
    return r;
}

// ---------------- prep ----------------
__global__ void prep_kernel(
    const float* __restrict__ Wk, const float* __restrict__ kg, const float* __restrict__ kb,
    const float* __restrict__ km, const float* __restrict__ kvv,
    const float* __restrict__ Wq, const float* __restrict__ qg, const float* __restrict__ qb,
    const float* __restrict__ qm, const float* __restrict__ qv,
    const float* __restrict__ Wv, const float* __restrict__ vg, const float* __restrict__ vb,
    const float* __restrict__ vm, const float* __restrict__ vv)
{
    int o = blockIdx.x, m = blockIdx.y, i = threadIdx.x;
    const float *W, *ga, *be, *me, *va;
    if (m == 0)      { W = Wq; ga = qg; be = qb; me = qm; va = qv; }
    else if (m == 1) { W = Wk; ga = kg; be = kb; me = km; va = kvv; }
    else             { W = Wv; ga = vg; be = vb; me = vm; va = vv; }
    float inv = ga[o] / sqrtf(va[o] + EPSV);
    float a = inv * W[o*CC + i];
    if (m == 0)      { g_Aq[o*CC + i] = a;  if (i == 0) g_bq[o] = be[o] - me[o]*inv; }
    else if (m == 1) { g_Ak[o*CC + i] = a;  if (i == 0) g_bk[o] = be[o] - me[o]*inv; }
    else             { g_AvT[i*CC + o] = a; if (i == 0) g_bv[o] = be[o] - me[o]*inv; }
}

// ---------------- rowsum ----------------
__global__ void rowsum_kernel(const float* __restrict__ x) {
    int c = blockIdx.x, n = blockIdx.y, t = threadIdx.x;
    const float4* xr = (const float4*)(x + ((size_t)n*CC + c)*SS);
    float acc = 0.f;
    for (int i = t; i < SS/4; i += 256) {
        float4 v = xr[i];
        acc += (v.x + v.y) + (v.z + v.w);
    }
    float tot = blockReduceSum(acc);
    if (t == 0) g_s[n*CC + c] = tot;
}

// ---------------- gram via 3xTF32 WMMA, pre-split staging, symmetry ----------------
#define GLD 36
#define GRAM_SMEM (4*128*GLD*4)   /* 73728 B: Ah, Al, Bh, Bl */
__global__ void __launch_bounds__(256, 2) gram_wmma_kernel(const float* __restrict__ x) {
    extern __shared__ float sm[];
    float* Ah = sm;
    float* Al = Ah + 128*GLD;
    const int bx = blockIdx.x;                 // 0:(0,0) 1:(0,1) 2:(1,1)
    const int bi = (bx == 2) ? 1 : 0;
    const int bj = (bx == 0) ? 0 : 1;
    const bool diag = (bi == bj);
    float* Bh = diag ? Ah : (Al + 128*GLD);
    float* Bl = diag ? Al : (Al + 2*128*GLD);

    const int tid = threadIdx.x, w = tid >> 5;
    const int wm = w >> 1, wn = w & 1;         // 4x2 warps -> 32x64 tiles
    const int zk = blockIdx.y, n = blockIdx.z;
    const int s0 = zk * (SS / KSPLIT);

    const int row = tid >> 1, part = tid & 1;
    const float* xa = x + ((size_t)n*CC + bi*128 + row)*SS + s0 + part*16;
    const float* xb = x + ((size_t)n*CC + bj*128 + row)*SS + s0 + part*16;

    wmma::fragment<wmma::accumulator, 16, 16, 8, float> acc[2][4];
#pragma unroll
    for (int i = 0; i < 2; i++)
#pragma unroll
        for (int j = 0; j < 4; j++) wmma::fill_fragment(acc[i][j], 0.0f);

    for (int t = 0; t < SS/KSPLIT; t += 32) {
#pragma unroll
        for (int q = 0; q < 4; q++) {
            float4 v = *(const float4*)(xa + t + q*4);
            int o = row*GLD + part*16 + q*4;
            split2(v.x, Ah[o+0], Al[o+0]); split2(v.y, Ah[o+1], Al[o+1]);
            split2(v.z, Ah[o+2], Al[o+2]); split2(v.w, Ah[o+3], Al[o+3]);
        }
        if (!diag) {
#pragma unroll
            for (int q = 0; q < 4; q++) {
                float4 v = *(const float4*)(xb + t + q*4);
                int o = row*GLD + part*16 + q*4;
                split2(v.x, Bh[o+0], Bl[o+0]); split2(v.y, Bh[o+1], Bl[o+1]);
                split2(v.z, Bh[o+2], Bl[o+2]); split2(v.w, Bh[o+3], Bl[o+3]);
            }
        }
        __syncthreads();
#pragma unroll
        for (int ks = 0; ks < 4; ks++) {
            wmma::fragment<wmma::matrix_a, 16, 16, 8, wmma::precision::tf32, wmma::row_major> ah[2], al[2];
            wmma::fragment<wmma::matrix_b, 16, 16, 8, wmma::precision::tf32, wmma::col_major> bh[4], bl[4];
#pragma unroll
            for (int i = 0; i < 2; i++) {
                wmma::load_matrix_sync(ah[i], &Ah[(wm*32 + i*16)*GLD + ks*8], GLD);
                wmma::load_matrix_sync(al[i], &Al[(wm*32 + i*16)*GLD + ks*8], GLD);
            }
#pragma unroll
            for (int j = 0; j < 4; j++) {
                wmma::load_matrix_sync(bh[j], &Bh[(wn*64 + j*16)*GLD + ks*8], GLD);
                wmma::load_matrix_sync(bl[j], &Bl[(wn*64 + j*16)*GLD + ks*8], GLD);
            }
#pragma unroll
            for (int i = 0; i < 2; i++)
#pragma unroll
                for (int j = 0; j < 4; j++) {
                    wmma::mma_sync(acc[i][j], ah[i], bl[j], acc[i][j]);
                    wmma::mma_sync(acc[i][j], al[i], bh[j], acc[i][j]);
                    wmma::mma_sync(acc[i][j], ah[i], bh[j], acc[i][j]);
                }
        }
        __syncthreads();
    }

    float* gp = g_Gp + ((size_t)zk*BB + n)*CC*CC;
#pragma unroll
    for (int i = 0; i < 2; i++)
#pragma unroll
        for (int j = 0; j < 4; j++) {
            wmma::store_matrix_sync(
                gp + (size_t)(bi*128 + wm*32 + i*16)*CC + bj*128 + wn*64 + j*16,
                acc[i][j], CC, wmma::mem_row_major);
            if (!diag)   // mirror into (bj,bi): transposed = col_major store
                wmma::store_matrix_sync(
                    gp + (size_t)(bj*128 + wn*64 + j*16)*CC + bi*128 + wm*32 + i*16,
                    acc[i][j], CC, wmma::mem_col_major);
        }
}

// ---------------- reduce gram partials ----------------
__global__ void reduceG_kernel() {
    size_t i = (size_t)blockIdx.x*256 + threadIdx.x;
    float s = 0.f;
#pragma unroll
    for (int z = 0; z < KSPLIT; z++) s += g_Gp[(size_t)z*(BB*CC*CC) + i];
    g_G[i] = s;
}

// ---------------- middle chain: 256^3 NT GEMM (SIMT fp32) ----------------
__global__ void __launch_bounds__(256) gemm256_nt_kernel(int mode) {
    __shared__ float As[16*64];
    __shared__ float Bs[16*64];
    int bj = blockIdx.x, bi = blockIdx.y, n = blockIdx.z;
    int tid = threadIdx.x, tx = tid & 15, ty = tid >> 4;
    int lrow = tid >> 2, lc4 = tid & 3;

    const float* A; const float* Bm; float* Out;
    if (mode == 0)      { A = g_Aq;                  Bm = g_G + (size_t)n*CC*CC; Out = g_P + (size_t)n*CC*CC; }
    else if (mode == 1) { A = g_P + (size_t)n*CC*CC; Bm = g_Ak;                  Out = g_L + (size_t)n*CC*CC; }
    else                { A = g_L + (size_t)n*CC*CC; Bm = g_AvT;                 Out = g_M + (size_t)n*CC*CC; }

    const float* ap = A  + (size_t)(bi*64 + lrow)*CC + lc4*4;
    const float* bp = Bm + (size_t)(bj*64 + lrow)*CC + lc4*4;

    float acc[4][4] = {};
    float4 a = *(const float4*)ap;
    float4 b = *(const float4*)bp;

    for (int kc = 0; kc < CC; kc += 16) {
        As[(lc4*4+0)*64 + lrow] = a.x;  As[(lc4*4+1)*64 + lrow] = a.y;
        As[(lc4*4+2)*64 + lrow] = a.z;  As[(lc4*4+3)*64 + lrow] = a.w;
        Bs[(lc4*4+0)*64 + lrow] = b.x;  Bs[(lc4*4+1)*64 + lrow] = b.y;
        Bs[(lc4*4+2)*64 + lrow] = b.z;  Bs[(lc4*4+3)*64 + lrow] = b.w;
        __syncthreads();
        int kn = (kc + 16 < CC) ? kc + 16 : kc;
        a = *(const float4*)(ap + kn);
        b = *(const float4*)(bp + kn);
#pragma unroll
        for (int kk = 0; kk < 16; kk++) {
            float4 av = *(const float4*)&As[kk*64 + ty*4];
            float4 bv = *(const float4*)&Bs[kk*64 + tx*4];
            acc[0][0] += av.x*bv.x; acc[0][1] += av.x*bv.y; acc[0][2] += av.x*bv.z; acc[0][3] += av.x*bv.w;
            acc[1][0] += av.y*bv.x; acc[1][1] += av.y*bv.y; acc[1][2] += av.y*bv.z; acc[1][3] += av.y*bv.w;
            acc[2][0] += av.z*bv.x; acc[2][1] += av.z*bv.y; acc[2][2] += av.z*bv.z; acc[2][3] += av.z*bv.w;
            acc[3][0] += av.w*bv.x; acc[3][1] += av.w*bv.y; acc[3][2] += av.w*bv.z; acc[3][3] += av.w*bv.w;
        }
        __syncthreads();
    }

    int row = bi*64 + ty*4, col = bj*64 + tx*4;
    if (mode == 1) {
#pragma unroll
        for (int u = 0; u < 4; u++) {
            float uu = g_u[n*CC + row + u], bb = g_bq[row + u];
#pragma unroll
            for (int v = 0; v < 4; v++) {
                float bk = g_bk[col + v];
                acc[u][v] += uu*bk + bb*(g_w[n*CC + col + v] + (float)SS*bk);
            }
        }
    } else if (mode == 2) {
#pragma unroll
        for (int u = 0; u < 4; u++)
#pragma unroll
            for (int v = 0; v < 4; v++)
                if (row + u == col + v) acc[u][v] += 1.0f;
    }

    float* out = Out + (size_t)row*CC + col;
#pragma unroll
    for (int u = 0; u < 4; u++)
        *(float4*)(out + (size_t)u*CC) = make_float4(acc[u][0], acc[u][1], acc[u][2], acc[u][3]);
}

// ---------------- matvecs ----------------
__global__ void matvec_kernel(int mode) {
    int r = blockIdx.x, n = blockIdx.y, t = threadIdx.x;
    const float* Arow; const float* vec; float* out;
    if (mode == 0)      { Arow = g_Aq + (size_t)r*CC;         vec = g_s + n*CC; out = g_u  + n*CC + r; }
    else if (mode == 1) { Arow = g_Ak + (size_t)r*CC;         vec = g_s + n*CC; out = g_w  + n*CC + r; }
    else                { Arow = g_L + ((size_t)n*CC + r)*CC; vec = g_bv;       out = g_cv + n*CC + r; }
    float p = Arow[t] * vec[t];
    float tot = blockReduceSum(p);
    if (t == 0) *out = tot;
}

// ---------------- softmax ----------------
__global__ void softmax_kernel() {
    int r = blockIdx.x, n = blockIdx.y, t = threadIdx.x;
    float* row = g_L + ((size_t)n*CC + r)*CC;
    float v = row[t];
    float m = blockReduceMax(v);
    float e = expf(v - m);
    float ss = blockReduceSum(e);
    row[t] = e / ss;
}

// ---------------- out = (M+I) @ X + c via 3xTF32 WMMA, pre-split staging ----------------
#define OLDA 36
#define OLDB 132
#define OUT_SMEM ((2*128*OLDA + 2*32*OLDB) * 4)   /* 70656 B; Cs (128*OLDB*4=67584) reuses it */
__global__ void __launch_bounds__(256, 2) out_wmma_kernel(const float* __restrict__ x,
                                                          float* __restrict__ out) {
    extern __shared__ float sm[];
    float* Ahs = sm;                    // 128 x OLDA
    float* Als = Ahs + 128*OLDA;
    float* Bhs = Als + 128*OLDA;        // 32 x OLDB
    float* Bls = Bhs + 32*OLDB;
    float* Cs  = sm;                    // 128 x OLDB (after loop)

    const int tid = threadIdx.x, w = tid >> 5;
    const int wm = w >> 1, wn = w & 1;
    const int bs = blockIdx.x, bc = blockIdx.y, n = blockIdx.z;
    const int s0 = bs*128, c0 = bc*128;

    const float* Mfb = g_M + (size_t)n*CC*CC;
    const float* Xb  = x + (size_t)n*CC*SS;

    wmma::fragment<wmma::accumulator, 16, 16, 8, float> acc[2][4];
#pragma unroll
    for (int i = 0; i < 2; i++)
#pragma unroll
        for (int j = 0; j < 4; j++) wmma::fill_fragment(acc[i][j], 0.0f);

    const int arow = tid >> 1, apart = tid & 1;

    for (int kb = 0; kb < CC; kb += 32) {
#pragma unroll
        for (int q = 0; q < 4; q++) {
            float4 v = *(const float4*)(Mfb + (size_t)(c0 + arow)*CC + kb + apart*16 + q*4);
            int o = arow*OLDA + apart*16 + q*4;
            split2(v.x, Ahs[o+0], Als[o+0]); split2(v.y, Ahs[o+1], Als[o+1]);
            split2(v.z, Ahs[o+2], Als[o+2]); split2(v.w, Ahs[o+3], Als[o+3]);
        }
#pragma unroll
        for (int i = 0; i < 4; i++) {
            int idx = i*256 + tid;
            int r = idx >> 5, c4 = idx & 31;
            float4 v = *(const float4*)(Xb + (size_t)(kb + r)*SS + s0 + c4*4);
            int o = r*OLDB + c4*4;
            split2(v.x, Bhs[o+0], Bls[o+0]); split2(v.y, Bhs[o+1], Bls[o+1]);
            split2(v.z, Bhs[o+2], Bls[o+2]); split2(v.w, Bhs[o+3], Bls[o+3]);
        }
        __syncthreads();
#pragma unroll
        for (int ks = 0; ks < 4; ks++) {
            wmma::fragment<wmma::matrix_a, 16, 16, 8, wmma::precision::tf32, wmma::row_major> ah[2], al[2];
            wmma::fragment<wmma::matrix_b, 16, 16, 8, wmma::precision::tf32, wmma::row_major> bh[4], bl[4];
#pragma unroll
            for (int i = 0; i < 2; i++) {
                wmma::load_matrix_sync(ah[i], &Ahs[(wm*32 + i*16)*OLDA + ks*8], OLDA);
                wmma::load_matrix_sync(al[i], &Als[(wm*32 + i*16)*OLDA + ks*8], OLDA);
            }
#pragma unroll
            for (int j = 0; j < 4; j++) {
                wmma::load_matrix_sync(bh[j], &Bhs[(ks*8)*OLDB + wn*64 + j*16], OLDB);
                wmma::load_matrix_sync(bl[j], &Bls[(ks*8)*OLDB + wn*64 + j*16], OLDB);
            }
#pragma unroll
            for (int i = 0; i < 2; i++)
#pragma unroll
                for (int j = 0; j < 4; j++) {
                    wmma::mma_sync(acc[i][j], ah[i], bl[j], acc[i][j]);
                    wmma::mma_sync(acc[i][j], al[i], bh[j], acc[i][j]);
                    wmma::mma_sync(acc[i][j], ah[i], bh[j], acc[i][j]);
                }
        }
        __syncthreads();
    }

#pragma unroll
    for (int i = 0; i < 2; i++)
#pragma unroll
        for (int j = 0; j < 4; j++)
            wmma::store_matrix_sync(&Cs[(wm*32 + i*16)*OLDB + wn*64 + j*16],
                                    acc[i][j], OLDB, wmma::mem_row_major);
    __syncthreads();

    const int crow = tid >> 1, cpart = tid & 1;
    float cv = g_cv[n*CC + c0 + crow];
    float* op = out + ((size_t)n*CC + c0 + crow)*SS + s0 + cpart*64;
#pragma unroll
    for (int q = 0; q < 16; q++) {
        float4 v = *(float4*)&Cs[crow*OLDB + cpart*64 + q*4];
        v.x += cv; v.y += cv; v.z += cv; v.w += cv;
        *(float4*)(op + q*4) = v;
    }
}

// ---------------- launcher ----------------
extern "C" void kernel_launch(void* const* d_in, const int* in_sizes, int n_in,
                              void* d_out, int out_size) {
    const float* x   = (const float*)d_in[0];
    const float* Wk  = (const float*)d_in[1];
    const float* kg  = (const float*)d_in[2];
    const float* kb  = (const float*)d_in[3];
    const float* km  = (const float*)d_in[4];
    const float* kv  = (const float*)d_in[5];
    const float* Wq  = (const float*)d_in[6];
    const float* qg  = (const float*)d_in[7];
    const float* qb  = (const float*)d_in[8];
    const float* qm  = (const float*)d_in[9];
    const float* qv  = (const float*)d_in[10];
    const float* Wv  = (const float*)d_in[11];
    const float* vg  = (const float*)d_in[12];
    const float* vb  = (const float*)d_in[13];
    const float* vm  = (const float*)d_in[14];
    const float* vv  = (const float*)d_in[15];
    float* out = (float*)d_out;

    cudaFuncSetAttribute(gram_wmma_kernel, cudaFuncAttributeMaxDynamicSharedMemorySize, GRAM_SMEM);
    cudaFuncSetAttribute(out_wmma_kernel,  cudaFuncAttributeMaxDynamicSharedMemorySize, OUT_SMEM);

    prep_kernel<<<dim3(CC, 3), CC>>>(Wk, kg, kb, km, kv, Wq, qg, qb, qm, qv, Wv, vg, vb, vm, vv);
    rowsum_kernel<<<dim3(CC, BB), 256>>>(x);
    matvec_kernel<<<dim3(CC, BB), 256>>>(0);                      // u = Aq @ s
    gram_wmma_kernel<<<dim3(3, KSPLIT, BB), 256, GRAM_SMEM>>>(x); // <- profiled slot
    reduceG_kernel<<<BB*CC*CC/256, 256>>>();
    gemm256_nt_kernel<<<dim3(4, 4, BB), 256>>>(0);   // P = Aq @ G
    matvec_kernel<<<dim3(CC, BB), 256>>>(1);         // w = Ak @ s
    gemm256_nt_kernel<<<dim3(4, 4, BB), 256>>>(1);   // L = P @ Ak^T + rank-1
    softmax_kernel<<<dim3(CC, BB), 256>>>();
    gemm256_nt_kernel<<<dim3(4, 4, BB), 256>>>(2);   // M = attn @ Av + I
    matvec_kernel<<<dim3(CC, BB), 256>>>(2);         // c = attn @ bv
    out_wmma_kernel<<<dim3(SS/128, CC/128, BB), 256, OUT_SMEM>>>(x, out);
}

// round 8
// speedup vs baseline: 3.1318x; 2.4988x over previous
#include <cuda_runtime.h>
#include <math.h>
#include <stdint.h>
#include <mma.h>
#include <cuda_fp16.h>

using namespace nvcuda;

#define BB 8
#define CC 256
#define SS 16384
#define EPSV 1e-5f
#define KSPLIT 16

// ---------------- scratch ----------------
__device__ float g_Gp[(size_t)KSPLIT*BB*CC*CC];
__device__ float g_G [BB*CC*CC];
__device__ float g_P [BB*CC*CC];
__device__ float g_L [BB*CC*CC];
__device__ float g_M [BB*CC*CC];
__device__ float g_Aq[CC*CC];
__device__ float g_Ak[CC*CC];
__device__ float g_AvT[CC*CC];
__device__ float g_bq[CC];
__device__ float g_bk[CC];
__device__ float g_bv[CC];
__device__ float g_s [BB*CC];
__device__ float g_u [BB*CC];
__device__ float g_w [BB*CC];
__device__ float g_cv[BB*CC];

// ---------------- fp16 two-term split (staging-time) ----------------
__device__ __forceinline__ void split2h(float v, __half& h, __half& l) {
    h = __float2half_rn(v);
    l = __float2half_rn(v - __half2float(h));
}

// ---------------- reductions ----------------
__device__ __forceinline__ float blockReduceSum(float v) {
    __shared__ float sh[8];
    int lane = threadIdx.x & 31, wid = threadIdx.x >> 5;
#pragma unroll
    for (int o = 16; o; o >>= 1) v += __shfl_xor_sync(0xffffffffu, v, o);
    if (lane == 0) sh[wid] = v;
    __syncthreads();
    float r = 0.f;
#pragma unroll
    for (int i = 0; i < 8; i++) r += sh[i];
    __syncthreads();
    return r;
}
__device__ __forceinline__ float blockReduceMax(float v) {
    __shared__ float sh[8];
    int lane = threadIdx.x & 31, wid = threadIdx.x >> 5;
#pragma unroll
    for (int o = 16; o; o >>= 1) v = fmaxf(v, __shfl_xor_sync(0xffffffffu, v, o));
    if (lane == 0) sh[wid] = v;
    __syncthreads();
    float r = -3.402823466e38f;
#pragma unroll
    for (int i = 0; i < 8; i++) r = fmaxf(r, sh[i]);
    __syncthreads();
    return r;
}

// ---------------- prep ----------------
__global__ void prep_kernel(
    const float* __restrict__ Wk, const float* __restrict__ kg, const float* __restrict__ kb,
    const float* __restrict__ km, const float* __restrict__ kvv,
    const float* __restrict__ Wq, const float* __restrict__ qg, const float* __restrict__ qb,
    const float* __restrict__ qm, const float* __restrict__ qv,
    const float* __restrict__ Wv, const float* __restrict__ vg, const float* __restrict__ vb,
    const float* __restrict__ vm, const float* __restrict__ vv)
{
    int o = blockIdx.x, m = blockIdx.y, i = threadIdx.x;
    const float *W, *ga, *be, *me, *va;
    if (m == 0)      { W = Wq; ga = qg; be = qb; me = qm; va = qv; }
    else if (m == 1) { W = Wk; ga = kg; be = kb; me = km; va = kvv; }
    else             { W = Wv; ga = vg; be = vb; me = vm; va = vv; }
    float inv = ga[o] / sqrtf(va[o] + EPSV);
    float a = inv * W[o*CC + i];
    if (m == 0)      { g_Aq[o*CC + i] = a;  if (i == 0) g_bq[o] = be[o] - me[o]*inv; }
    else if (m == 1) { g_Ak[o*CC + i] = a;  if (i == 0) g_bk[o] = be[o] - me[o]*inv; }
    else             { g_AvT[i*CC + o] = a; if (i == 0) g_bv[o] = be[o] - me[o]*inv; }
}

// ---------------- rowsum ----------------
__global__ void rowsum_kernel(const float* __restrict__ x) {
    int c = blockIdx.x, n = blockIdx.y, t = threadIdx.x;
    const float4* xr = (const float4*)(x + ((size_t)n*CC + c)*SS);
    float acc = 0.f;
    for (int i = t; i < SS/4; i += 256) {
        float4 v = xr[i];
        acc += (v.x + v.y) + (v.z + v.w);
    }
    float tot = blockReduceSum(acc);
    if (t == 0) g_s[n*CC + c] = tot;
}

// ---------------- gram via 3xFP16 WMMA (m16n16k16), pre-split staging, symmetry ----------------
#define GLDH 40
#define GRAM_SMEM (4*128*GLDH*2)   /* 40960 B: Ah, Al, Bh, Bl (half) */
__global__ void __launch_bounds__(256, 2) gram_wmma_kernel(const float* __restrict__ x) {
    extern __shared__ char smraw[];
    __half* Ah = (__half*)smraw;
    __half* Al = Ah + 128*GLDH;
    const int bx = blockIdx.x;                 // 0:(0,0) 1:(0,1) 2:(1,1)
    const int bi = (bx == 2) ? 1 : 0;
    const int bj = (bx == 0) ? 0 : 1;
    const bool diag = (bi == bj);
    __half* Bh = diag ? Ah : (Al + 128*GLDH);
    __half* Bl = diag ? Al : (Al + 2*128*GLDH);

    const int tid = threadIdx.x, w = tid >> 5;
    const int wm = w >> 1, wn = w & 1;         // 4x2 warps -> 32x64 tiles
    const int zk = blockIdx.y, n = blockIdx.z;
    const int s0 = zk * (SS / KSPLIT);

    const int row = tid >> 1, part = tid & 1;
    const float* xa = x + ((size_t)n*CC + bi*128 + row)*SS + s0 + part*16;
    const float* xb = x + ((size_t)n*CC + bj*128 + row)*SS + s0 + part*16;

    wmma::fragment<wmma::accumulator, 16, 16, 16, float> acc[2][4];
#pragma unroll
    for (int i = 0; i < 2; i++)
#pragma unroll
        for (int j = 0; j < 4; j++) wmma::fill_fragment(acc[i][j], 0.0f);

    for (int t = 0; t < SS/KSPLIT; t += 32) {
#pragma unroll
        for (int q = 0; q < 4; q++) {
            float4 v = *(const float4*)(xa + t + q*4);
            int o = row*GLDH + part*16 + q*4;
            split2h(v.x, Ah[o+0], Al[o+0]); split2h(v.y, Ah[o+1], Al[o+1]);
            split2h(v.z, Ah[o+2], Al[o+2]); split2h(v.w, Ah[o+3], Al[o+3]);
        }
        if (!diag) {
#pragma unroll
            for (int q = 0; q < 4; q++) {
                float4 v = *(const float4*)(xb + t + q*4);
                int o = row*GLDH + part*16 + q*4;
                split2h(v.x, Bh[o+0], Bl[o+0]); split2h(v.y, Bh[o+1], Bl[o+1]);
                split2h(v.z, Bh[o+2], Bl[o+2]); split2h(v.w, Bh[o+3], Bl[o+3]);
            }
        }
        __syncthreads();
#pragma unroll
        for (int ks = 0; ks < 2; ks++) {
            wmma::fragment<wmma::matrix_a, 16, 16, 16, __half, wmma::row_major> ah[2], al[2];
            wmma::fragment<wmma::matrix_b, 16, 16, 16, __half, wmma::col_major> bh[4], bl[4];
#pragma unroll
            for (int i = 0; i < 2; i++) {
                wmma::load_matrix_sync(ah[i], &Ah[(wm*32 + i*16)*GLDH + ks*16], GLDH);
                wmma::load_matrix_sync(al[i], &Al[(wm*32 + i*16)*GLDH + ks*16], GLDH);
            }
#pragma unroll
            for (int j = 0; j < 4; j++) {
                wmma::load_matrix_sync(bh[j], &Bh[(wn*64 + j*16)*GLDH + ks*16], GLDH);
                wmma::load_matrix_sync(bl[j], &Bl[(wn*64 + j*16)*GLDH + ks*16], GLDH);
            }
#pragma unroll
            for (int i = 0; i < 2; i++)
#pragma unroll
                for (int j = 0; j < 4; j++) {
                    wmma::mma_sync(acc[i][j], ah[i], bl[j], acc[i][j]);
                    wmma::mma_sync(acc[i][j], al[i], bh[j], acc[i][j]);
                    wmma::mma_sync(acc[i][j], ah[i], bh[j], acc[i][j]);
                }
        }
        __syncthreads();
    }

    float* gp = g_Gp + ((size_t)zk*BB + n)*CC*CC;
#pragma unroll
    for (int i = 0; i < 2; i++)
#pragma unroll
        for (int j = 0; j < 4; j++) {
            wmma::store_matrix_sync(
                gp + (size_t)(bi*128 + wm*32 + i*16)*CC + bj*128 + wn*64 + j*16,
                acc[i][j], CC, wmma::mem_row_major);
            if (!diag)
                wmma::store_matrix_sync(
                    gp + (size_t)(bj*128 + wn*64 + j*16)*CC + bi*128 + wm*32 + i*16,
                    acc[i][j], CC, wmma::mem_col_major);
        }
}

// ---------------- reduce gram partials ----------------
__global__ void reduceG_kernel() {
    size_t i = (size_t)blockIdx.x*256 + threadIdx.x;
    float s = 0.f;
#pragma unroll
    for (int z = 0; z < KSPLIT; z++) s += g_Gp[(size_t)z*(BB*CC*CC) + i];
    g_G[i] = s;
}

// ---------------- middle chain: 256^3 NT GEMM (SIMT fp32) ----------------
__global__ void __launch_bounds__(256) gemm256_nt_kernel(int mode) {
    __shared__ float As[16*64];
    __shared__ float Bs[16*64];
    int bj = blockIdx.x, bi = blockIdx.y, n = blockIdx.z;
    int tid = threadIdx.x, tx = tid & 15, ty = tid >> 4;
    int lrow = tid >> 2, lc4 = tid & 3;

    const float* A; const float* Bm; float* Out;
    if (mode == 0)      { A = g_Aq;                  Bm = g_G + (size_t)n*CC*CC; Out = g_P + (size_t)n*CC*CC; }
    else if (mode == 1) { A = g_P + (size_t)n*CC*CC; Bm = g_Ak;                  Out = g_L + (size_t)n*CC*CC; }
    else                { A = g_L + (size_t)n*CC*CC; Bm = g_AvT;                 Out = g_M + (size_t)n*CC*CC; }

    const float* ap = A  + (size_t)(bi*64 + lrow)*CC + lc4*4;
    const float* bp = Bm + (size_t)(bj*64 + lrow)*CC + lc4*4;

    float acc[4][4] = {};
    float4 a = *(const float4*)ap;
    float4 b = *(const float4*)bp;

    for (int kc = 0; kc < CC; kc += 16) {
        As[(lc4*4+0)*64 + lrow] = a.x;  As[(lc4*4+1)*64 + lrow] = a.y;
        As[(lc4*4+2)*64 + lrow] = a.z;  As[(lc4*4+3)*64 + lrow] = a.w;
        Bs[(lc4*4+0)*64 + lrow] = b.x;  Bs[(lc4*4+1)*64 + lrow] = b.y;
        Bs[(lc4*4+2)*64 + lrow] = b.z;  Bs[(lc4*4+3)*64 + lrow] = b.w;
        __syncthreads();
        int kn = (kc + 16 < CC) ? kc + 16 : kc;
        a = *(const float4*)(ap + kn);
        b = *(const float4*)(bp + kn);
#pragma unroll
        for (int kk = 0; kk < 16; kk++) {
            float4 av = *(const float4*)&As[kk*64 + ty*4];
            float4 bv = *(const float4*)&Bs[kk*64 + tx*4];
            acc[0][0] += av.x*bv.x; acc[0][1] += av.x*bv.y; acc[0][2] += av.x*bv.z; acc[0][3] += av.x*bv.w;
            acc[1][0] += av.y*bv.x; acc[1][1] += av.y*bv.y; acc[1][2] += av.y*bv.z; acc[1][3] += av.y*bv.w;
            acc[2][0] += av.z*bv.x; acc[2][1] += av.z*bv.y; acc[2][2] += av.z*bv.z; acc[2][3] += av.z*bv.w;
            acc[3][0] += av.w*bv.x; acc[3][1] += av.w*bv.y; acc[3][2] += av.w*bv.z; acc[3][3] += av.w*bv.w;
        }
        __syncthreads();
    }

    int row = bi*64 + ty*4, col = bj*64 + tx*4;
    if (mode == 1) {
#pragma unroll
        for (int u = 0; u < 4; u++) {
            float uu = g_u[n*CC + row + u], bb = g_bq[row + u];
#pragma unroll
            for (int v = 0; v < 4; v++) {
                float bk = g_bk[col + v];
                acc[u][v] += uu*bk + bb*(g_w[n*CC + col + v] + (float)SS*bk);
            }
        }
    } else if (mode == 2) {
#pragma unroll
        for (int u = 0; u < 4; u++)
#pragma unroll
            for (int v = 0; v < 4; v++)
                if (row + u == col + v) acc[u][v] += 1.0f;
    }

    float* out = Out + (size_t)row*CC + col;
#pragma unroll
    for (int u = 0; u < 4; u++)
        *(float4*)(out + (size_t)u*CC) = make_float4(acc[u][0], acc[u][1], acc[u][2], acc[u][3]);
}

// ---------------- matvecs ----------------
__global__ void matvec_kernel(int mode) {
    int r = blockIdx.x, n = blockIdx.y, t = threadIdx.x;
    const float* Arow; const float* vec; float* out;
    if (mode == 0)      { Arow = g_Aq + (size_t)r*CC;         vec = g_s + n*CC; out = g_u  + n*CC + r; }
    else if (mode == 1) { Arow = g_Ak + (size_t)r*CC;         vec = g_s + n*CC; out = g_w  + n*CC + r; }
    else                { Arow = g_L + ((size_t)n*CC + r)*CC; vec = g_bv;       out = g_cv + n*CC + r; }
    float p = Arow[t] * vec[t];
    float tot = blockReduceSum(p);
    if (t == 0) *out = tot;
}

// ---------------- softmax ----------------
__global__ void softmax_kernel() {
    int r = blockIdx.x, n = blockIdx.y, t = threadIdx.x;
    float* row = g_L + ((size_t)n*CC + r)*CC;
    float v = row[t];
    float m = blockReduceMax(v);
    float e = expf(v - m);
    float ss = blockReduceSum(e);
    row[t] = e / ss;
}

// ---------------- out = (M+I) @ X + c via 3xFP16 WMMA, pre-split staging ----------------
#define OLDAH 40            /* A staging stride (halves) */
#define OLDBH 136           /* B staging stride (halves) */
#define OLDC  132           /* C epilogue stride (floats) */
#define OUT_SMEM (128*OLDC*4)   /* 67584 B >= staging (2*128*40 + 2*32*136)*2 = 37888 */
__global__ void __launch_bounds__(256, 2) out_wmma_kernel(const float* __restrict__ x,
                                                          float* __restrict__ out) {
    extern __shared__ char smraw[];
    __half* Ahs = (__half*)smraw;           // 128 x OLDAH
    __half* Als = Ahs + 128*OLDAH;
    __half* Bhs = Als + 128*OLDAH;          // 32 x OLDBH
    __half* Bls = Bhs + 32*OLDBH;
    float*  Cs  = (float*)smraw;            // 128 x OLDC (after loop)

    const int tid = threadIdx.x, w = tid >> 5;
    const int wm = w >> 1, wn = w & 1;
    const int bs = blockIdx.x, bc = blockIdx.y, n = blockIdx.z;
    const int s0 = bs*128, c0 = bc*128;

    const float* Mfb = g_M + (size_t)n*CC*CC;
    const float* Xb  = x + (size_t)n*CC*SS;

    wmma::fragment<wmma::accumulator, 16, 16, 16, float> acc[2][4];
#pragma unroll
    for (int i = 0; i < 2; i++)
#pragma unroll
        for (int j = 0; j < 4; j++) wmma::fill_fragment(acc[i][j], 0.0f);

    const int arow = tid >> 1, apart = tid & 1;

    for (int kb = 0; kb < CC; kb += 32) {
#pragma unroll
        for (int q = 0; q < 4; q++) {
            float4 v = *(const float4*)(Mfb + (size_t)(c0 + arow)*CC + kb + apart*16 + q*4);
            int o = arow*OLDAH + apart*16 + q*4;
            split2h(v.x, Ahs[o+0], Als[o+0]); split2h(v.y, Ahs[o+1], Als[o+1]);
            split2h(v.z, Ahs[o+2], Als[o+2]); split2h(v.w, Ahs[o+3], Als[o+3]);
        }
#pragma unroll
        for (int i = 0; i < 4; i++) {
            int idx = i*256 + tid;
            int r = idx >> 5, c4 = idx & 31;
            float4 v = *(const float4*)(Xb + (size_t)(kb + r)*SS + s0 + c4*4);
            int o = r*OLDBH + c4*4;
            split2h(v.x, Bhs[o+0], Bls[o+0]); split2h(v.y, Bhs[o+1], Bls[o+1]);
            split2h(v.z, Bhs[o+2], Bls[o+2]); split2h(v.w, Bhs[o+3], Bls[o+3]);
        }
        __syncthreads();
#pragma unroll
        for (int ks = 0; ks < 2; ks++) {
            wmma::fragment<wmma::matrix_a, 16, 16, 16, __half, wmma::row_major> ah[2], al[2];
            wmma::fragment<wmma::matrix_b, 16, 16, 16, __half, wmma::row_major> bh[4], bl[4];
#pragma unroll
            for (int i = 0; i < 2; i++) {
                wmma::load_matrix_sync(ah[i], &Ahs[(wm*32 + i*16)*OLDAH + ks*16], OLDAH);
                wmma::load_matrix_sync(al[i], &Als[(wm*32 + i*16)*OLDAH + ks*16], OLDAH);
            }
#pragma unroll
            for (int j = 0; j < 4; j++) {
                wmma::load_matrix_sync(bh[j], &Bhs[(ks*16)*OLDBH + wn*64 + j*16], OLDBH);
                wmma::load_matrix_sync(bl[j], &Bls[(ks*16)*OLDBH + wn*64 + j*16], OLDBH);
            }
#pragma unroll
            for (int i = 0; i < 2; i++)
#pragma unroll
                for (int j = 0; j < 4; j++) {
                    wmma::mma_sync(acc[i][j], ah[i], bl[j], acc[i][j]);
                    wmma::mma_sync(acc[i][j], al[i], bh[j], acc[i][j]);
                    wmma::mma_sync(acc[i][j], ah[i], bh[j], acc[i][j]);
                }
        }
        __syncthreads();
    }

#pragma unroll
    for (int i = 0; i < 2; i++)
#pragma unroll
        for (int j = 0; j < 4; j++)
            wmma::store_matrix_sync(&Cs[(wm*32 + i*16)*OLDC + wn*64 + j*16],
                                    acc[i][j], OLDC, wmma::mem_row_major);
    __syncthreads();

    const int crow = tid >> 1, cpart = tid & 1;
    float cv = g_cv[n*CC + c0 + crow];
    float* op = out + ((size_t)n*CC + c0 + crow)*SS + s0 + cpart*64;
#pragma unroll
    for (int q = 0; q < 16; q++) {
        float4 v = *(float4*)&Cs[crow*OLDC + cpart*64 + q*4];
        v.x += cv; v.y += cv; v.z += cv; v.w += cv;
        *(float4*)(op + q*4) = v;
    }
}

// ---------------- launcher ----------------
extern "C" void kernel_launch(void* const* d_in, const int* in_sizes, int n_in,
                              void* d_out, int out_size) {
    const float* x   = (const float*)d_in[0];
    const float* Wk  = (const float*)d_in[1];
    const float* kg  = (const float*)d_in[2];
    const float* kb  = (const float*)d_in[3];
    const float* km  = (const float*)d_in[4];
    const float* kv  = (const float*)d_in[5];
    const float* Wq  = (const float*)d_in[6];
    const float* qg  = (const float*)d_in[7];
    const float* qb  = (const float*)d_in[8];
    const float* qm  = (const float*)d_in[9];
    const float* qv  = (const float*)d_in[10];
    const float* Wv  = (const float*)d_in[11];
    const float* vg  = (const float*)d_in[12];
    const float* vb  = (const float*)d_in[13];
    const float* vm  = (const float*)d_in[14];
    const float* vv  = (const float*)d_in[15];
    float* out = (float*)d_out;

    cudaFuncSetAttribute(gram_wmma_kernel, cudaFuncAttributeMaxDynamicSharedMemorySize, GRAM_SMEM);
    cudaFuncSetAttribute(out_wmma_kernel,  cudaFuncAttributeMaxDynamicSharedMemorySize, OUT_SMEM);

    prep_kernel<<<dim3(CC, 3), CC>>>(Wk, kg, kb, km, kv, Wq, qg, qb, qm, qv, Wv, vg, vb, vm, vv);
    rowsum_kernel<<<dim3(CC, BB), 256>>>(x);
    matvec_kernel<<<dim3(CC, BB), 256>>>(0);                      // u = Aq @ s
    gram_wmma_kernel<<<dim3(3, KSPLIT, BB), 256, GRAM_SMEM>>>(x); // <- profiled slot
    reduceG_kernel<<<BB*CC*CC/256, 256>>>();
    gemm256_nt_kernel<<<dim3(4, 4, BB), 256>>>(0);   // P = Aq @ G
    matvec_kernel<<<dim3(CC, BB), 256>>>(1);         // w = Ak @ s
    gemm256_nt_kernel<<<dim3(4, 4, BB), 256>>>(1);   // L = P @ Ak^T + rank-1
    softmax_kernel<<<dim3(CC, BB), 256>>>();
    gemm256_nt_kernel<<<dim3(4, 4, BB), 256>>>(2);   // M = attn @ Av + I
    matvec_kernel<<<dim3(CC, BB), 256>>>(2);         // c = attn @ bv
    out_wmma_kernel<<<dim3(SS/128, CC/128, BB), 256, OUT_SMEM>>>(x, out);
}

// round 9
// speedup vs baseline: 3.4472x; 1.1007x over previous
#include <cuda_runtime.h>
#include <math.h>
#include <stdint.h>
#include <mma.h>
#include <cuda_fp16.h>

using namespace nvcuda;

#define BB 8
#define CC 256
#define SS 16384
#define EPSV 1e-5f
#define KSPLIT 16

// ---------------- scratch ----------------
__device__ float g_Gp[(size_t)KSPLIT*BB*CC*CC];
__device__ float g_G [BB*CC*CC];
__device__ float g_P [BB*CC*CC];
__device__ float g_L [BB*CC*CC];
__device__ float g_M [BB*CC*CC];
__device__ float g_Aq[CC*CC];
__device__ float g_Ak[CC*CC];
__device__ float g_AvT[CC*CC];
__device__ float g_bq[CC];
__device__ float g_bk[CC];
__device__ float g_bv[CC];
__device__ float g_s [BB*CC];
__device__ float g_u [BB*CC];
__device__ float g_w [BB*CC];
__device__ float g_cv[BB*CC];

// ---------------- fp16 two-term split ----------------
__device__ __forceinline__ void split2h(float v, __half& h, __half& l) {
    h = __float2half_rn(v);
    l = __float2half_rn(v - __half2float(h));
}

// ---------------- reductions ----------------
__device__ __forceinline__ float blockReduceSum(float v) {
    __shared__ float sh[8];
    int lane = threadIdx.x & 31, wid = threadIdx.x >> 5;
#pragma unroll
    for (int o = 16; o; o >>= 1) v += __shfl_xor_sync(0xffffffffu, v, o);
    if (lane == 0) sh[wid] = v;
    __syncthreads();
    float r = 0.f;
#pragma unroll
    for (int i = 0; i < 8; i++) r += sh[i];
    __syncthreads();
    return r;
}
__device__ __forceinline__ float blockReduceMax(float v) {
    __shared__ float sh[8];
    int lane = threadIdx.x & 31, wid = threadIdx.x >> 5;
#pragma unroll
    for (int o = 16; o; o >>= 1) v = fmaxf(v, __shfl_xor_sync(0xffffffffu, v, o));
    if (lane == 0) sh[wid] = v;
    __syncthreads();
    float r = -3.402823466e38f;
#pragma unroll
    for (int i = 0; i < 8; i++) r = fmaxf(r, sh[i]);
    __syncthreads();
    return r;
}

// ---------------- prep ----------------
__global__ void prep_kernel(
    const float* __restrict__ Wk, const float* __restrict__ kg, const float* __restrict__ kb,
    const float* __restrict__ km, const float* __restrict__ kvv,
    const float* __restrict__ Wq, const float* __restrict__ qg, const float* __restrict__ qb,
    const float* __restrict__ qm, const float* __restrict__ qv,
    const float* __restrict__ Wv, const float* __restrict__ vg, const float* __restrict__ vb,
    const float* __restrict__ vm, const float* __restrict__ vv)
{
    int o = blockIdx.x, m = blockIdx.y, i = threadIdx.x;
    const float *W, *ga, *be, *me, *va;
    if (m == 0)      { W = Wq; ga = qg; be = qb; me = qm; va = qv; }
    else if (m == 1) { W = Wk; ga = kg; be = kb; me = km; va = kvv; }
    else             { W = Wv; ga = vg; be = vb; me = vm; va = vv; }
    float inv = ga[o] / sqrtf(va[o] + EPSV);
    float a = inv * W[o*CC + i];
    if (m == 0)      { g_Aq[o*CC + i] = a;  if (i == 0) g_bq[o] = be[o] - me[o]*inv; }
    else if (m == 1) { g_Ak[o*CC + i] = a;  if (i == 0) g_bk[o] = be[o] - me[o]*inv; }
    else             { g_AvT[i*CC + o] = a; if (i == 0) g_bv[o] = be[o] - me[o]*inv; }
}

// ---------------- rowsum ----------------
__global__ void rowsum_kernel(const float* __restrict__ x) {
    int c = blockIdx.x, n = blockIdx.y, t = threadIdx.x;
    const float4* xr = (const float4*)(x + ((size_t)n*CC + c)*SS);
    float acc = 0.f;
    for (int i = t; i < SS/4; i += 256) {
        float4 v = xr[i];
        acc += (v.x + v.y) + (v.z + v.w);
    }
    float tot = blockReduceSum(acc);
    if (t == 0) g_s[n*CC + c] = tot;
}

// ---------------- gram via 3xFP16 WMMA, 2-stage pipelined staging, symmetry ----------------
#define GLDH 40
#define GSTR (4*128*GLDH)                 /* halves per stage */
#define GRAM_SMEM (2*GSTR*2)              /* 81920 B */
__global__ void __launch_bounds__(256, 2) gram_wmma_kernel(const float* __restrict__ x) {
    extern __shared__ char smraw[];
    __half* S = (__half*)smraw;
    const int bx = blockIdx.x;                 // 0:(0,0) 1:(0,1) 2:(1,1)
    const int bi = (bx == 2) ? 1 : 0;
    const int bj = (bx == 0) ? 0 : 1;
    const bool diag = (bi == bj);

    const int tid = threadIdx.x, w = tid >> 5;
    const int wm = w >> 1, wn = w & 1;         // 4x2 warps -> 32x64 tiles
    const int zk = blockIdx.y, n = blockIdx.z;
    const int s0 = zk * (SS / KSPLIT);

    const int row = tid >> 1, part = tid & 1;
    const float* xa = x + ((size_t)n*CC + bi*128 + row)*SS + s0 + part*16;
    const float* xb = x + ((size_t)n*CC + bj*128 + row)*SS + s0 + part*16;

    wmma::fragment<wmma::accumulator, 16, 16, 16, float> acc[2][4];
#pragma unroll
    for (int i = 0; i < 2; i++)
#pragma unroll
        for (int j = 0; j < 4; j++) wmma::fill_fragment(acc[i][j], 0.0f);

    const int NT = SS/KSPLIT/32;   // 32 iterations

    auto stage = [&](int st, int t) {
        __half* Ah = S + st*GSTR;
        __half* Al = Ah + 128*GLDH;
        __half* Bh = Al + 128*GLDH;
        __half* Bl = Bh + 128*GLDH;
#pragma unroll
        for (int q = 0; q < 4; q++) {
            float4 v = *(const float4*)(xa + t*32 + q*4);
            int o = row*GLDH + part*16 + q*4;
            split2h(v.x, Ah[o+0], Al[o+0]); split2h(v.y, Ah[o+1], Al[o+1]);
            split2h(v.z, Ah[o+2], Al[o+2]); split2h(v.w, Ah[o+3], Al[o+3]);
        }
        if (!diag) {
#pragma unroll
            for (int q = 0; q < 4; q++) {
                float4 v = *(const float4*)(xb + t*32 + q*4);
                int o = row*GLDH + part*16 + q*4;
                split2h(v.x, Bh[o+0], Bl[o+0]); split2h(v.y, Bh[o+1], Bl[o+1]);
                split2h(v.z, Bh[o+2], Bl[o+2]); split2h(v.w, Bh[o+3], Bl[o+3]);
            }
        }
    };

    auto domma = [&](int st) {
        __half* Ah = S + st*GSTR;
        __half* Al = Ah + 128*GLDH;
        __half* Bh = diag ? Ah : (Al + 128*GLDH);
        __half* Bl = diag ? Al : (Al + 2*128*GLDH);
#pragma unroll
        for (int ks = 0; ks < 2; ks++) {
            wmma::fragment<wmma::matrix_a, 16, 16, 16, __half, wmma::row_major> ah[2], al[2];
            wmma::fragment<wmma::matrix_b, 16, 16, 16, __half, wmma::col_major> bh[4], bl[4];
#pragma unroll
            for (int i = 0; i < 2; i++) {
                wmma::load_matrix_sync(ah[i], &Ah[(wm*32 + i*16)*GLDH + ks*16], GLDH);
                wmma::load_matrix_sync(al[i], &Al[(wm*32 + i*16)*GLDH + ks*16], GLDH);
            }
#pragma unroll
            for (int j = 0; j < 4; j++) {
                wmma::load_matrix_sync(bh[j], &Bh[(wn*64 + j*16)*GLDH + ks*16], GLDH);
                wmma::load_matrix_sync(bl[j], &Bl[(wn*64 + j*16)*GLDH + ks*16], GLDH);
            }
#pragma unroll
            for (int i = 0; i < 2; i++)
#pragma unroll
                for (int j = 0; j < 4; j++) {
                    wmma::mma_sync(acc[i][j], ah[i], bl[j], acc[i][j]);
                    wmma::mma_sync(acc[i][j], al[i], bh[j], acc[i][j]);
                    wmma::mma_sync(acc[i][j], ah[i], bh[j], acc[i][j]);
                }
        }
    };

    stage(0, 0);
    __syncthreads();
    int st = 0;
    for (int t = 0; t < NT; t++) {
        if (t + 1 < NT) stage(st ^ 1, t + 1);
        domma(st);
        __syncthreads();
        st ^= 1;
    }

    float* gp = g_Gp + ((size_t)zk*BB + n)*CC*CC;
#pragma unroll
    for (int i = 0; i < 2; i++)
#pragma unroll
        for (int j = 0; j < 4; j++) {
            wmma::store_matrix_sync(
                gp + (size_t)(bi*128 + wm*32 + i*16)*CC + bj*128 + wn*64 + j*16,
                acc[i][j], CC, wmma::mem_row_major);
            if (!diag)
                wmma::store_matrix_sync(
                    gp + (size_t)(bj*128 + wn*64 + j*16)*CC + bi*128 + wm*32 + i*16,
                    acc[i][j], CC, wmma::mem_col_major);
        }
}

// ---------------- reduce gram partials ----------------
__global__ void reduceG_kernel() {
    size_t i = (size_t)blockIdx.x*256 + threadIdx.x;
    float s = 0.f;
#pragma unroll
    for (int z = 0; z < KSPLIT; z++) s += g_Gp[(size_t)z*(BB*CC*CC) + i];
    g_G[i] = s;
}

// ---------------- middle chain: 256^3 NT GEMM (SIMT fp32) ----------------
__global__ void __launch_bounds__(256) gemm256_nt_kernel(int mode) {
    __shared__ float As[16*64];
    __shared__ float Bs[16*64];
    int bj = blockIdx.x, bi = blockIdx.y, n = blockIdx.z;
    int tid = threadIdx.x, tx = tid & 15, ty = tid >> 4;
    int lrow = tid >> 2, lc4 = tid & 3;

    const float* A; const float* Bm; float* Out;
    if (mode == 0)      { A = g_Aq;                  Bm = g_G + (size_t)n*CC*CC; Out = g_P + (size_t)n*CC*CC; }
    else if (mode == 1) { A = g_P + (size_t)n*CC*CC; Bm = g_Ak;                  Out = g_L + (size_t)n*CC*CC; }
    else                { A = g_L + (size_t)n*CC*CC; Bm = g_AvT;                 Out = g_M + (size_t)n*CC*CC; }

    const float* ap = A  + (size_t)(bi*64 + lrow)*CC + lc4*4;
    const float* bp = Bm + (size_t)(bj*64 + lrow)*CC + lc4*4;

    float acc[4][4] = {};
    float4 a = *(const float4*)ap;
    float4 b = *(const float4*)bp;

    for (int kc = 0; kc < CC; kc += 16) {
        As[(lc4*4+0)*64 + lrow] = a.x;  As[(lc4*4+1)*64 + lrow] = a.y;
        As[(lc4*4+2)*64 + lrow] = a.z;  As[(lc4*4+3)*64 + lrow] = a.w;
        Bs[(lc4*4+0)*64 + lrow] = b.x;  Bs[(lc4*4+1)*64 + lrow] = b.y;
        Bs[(lc4*4+2)*64 + lrow] = b.z;  Bs[(lc4*4+3)*64 + lrow] = b.w;
        __syncthreads();
        int kn = (kc + 16 < CC) ? kc + 16 : kc;
        a = *(const float4*)(ap + kn);
        b = *(const float4*)(bp + kn);
#pragma unroll
        for (int kk = 0; kk < 16; kk++) {
            float4 av = *(const float4*)&As[kk*64 + ty*4];
            float4 bv = *(const float4*)&Bs[kk*64 + tx*4];
            acc[0][0] += av.x*bv.x; acc[0][1] += av.x*bv.y; acc[0][2] += av.x*bv.z; acc[0][3] += av.x*bv.w;
            acc[1][0] += av.y*bv.x; acc[1][1] += av.y*bv.y; acc[1][2] += av.y*bv.z; acc[1][3] += av.y*bv.w;
            acc[2][0] += av.z*bv.x; acc[2][1] += av.z*bv.y; acc[2][2] += av.z*bv.z; acc[2][3] += av.z*bv.w;
            acc[3][0] += av.w*bv.x; acc[3][1] += av.w*bv.y; acc[3][2] += av.w*bv.z; acc[3][3] += av.w*bv.w;
        }
        __syncthreads();
    }

    int row = bi*64 + ty*4, col = bj*64 + tx*4;
    if (mode == 1) {
#pragma unroll
        for (int u = 0; u < 4; u++) {
            float uu = g_u[n*CC + row + u], bb = g_bq[row + u];
#pragma unroll
            for (int v = 0; v < 4; v++) {
                float bk = g_bk[col + v];
                acc[u][v] += uu*bk + bb*(g_w[n*CC + col + v] + (float)SS*bk);
            }
        }
    } else if (mode == 2) {
#pragma unroll
        for (int u = 0; u < 4; u++)
#pragma unroll
            for (int v = 0; v < 4; v++)
                if (row + u == col + v) acc[u][v] += 1.0f;
    }

    float* out = Out + (size_t)row*CC + col;
#pragma unroll
    for (int u = 0; u < 4; u++)
        *(float4*)(out + (size_t)u*CC) = make_float4(acc[u][0], acc[u][1], acc[u][2], acc[u][3]);
}

// ---------------- matvecs ----------------
__global__ void matvec_kernel(int mode) {
    int r = blockIdx.x, n = blockIdx.y, t = threadIdx.x;
    const float* Arow; const float* vec; float* out;
    if (mode == 0)      { Arow = g_Aq + (size_t)r*CC;         vec = g_s + n*CC; out = g_u  + n*CC + r; }
    else if (mode == 1) { Arow = g_Ak + (size_t)r*CC;         vec = g_s + n*CC; out = g_w  + n*CC + r; }
    else                { Arow = g_L + ((size_t)n*CC + r)*CC; vec = g_bv;       out = g_cv + n*CC + r; }
    float p = Arow[t] * vec[t];
    float tot = blockReduceSum(p);
    if (t == 0) *out = tot;
}

// ---------------- softmax ----------------
__global__ void softmax_kernel() {
    int r = blockIdx.x, n = blockIdx.y, t = threadIdx.x;
    float* row = g_L + ((size_t)n*CC + r)*CC;
    float v = row[t];
    float m = blockReduceMax(v);
    float e = expf(v - m);
    float ss = blockReduceSum(e);
    row[t] = e / ss;
}

// ---------------- out = (M+I) @ X + c via 3xFP16 WMMA, 2-stage pipelined ----------------
#define OLDAH 40            /* A staging stride (halves) */
#define OLDBH 136           /* B staging stride (halves) */
#define OLDC  132           /* C epilogue stride (floats) */
#define OSTR (2*128*OLDAH + 2*32*OLDBH)      /* halves per stage = 18944 */
#define OUT_SMEM (2*OSTR*2 > 128*OLDC*4 ? 2*OSTR*2 : 128*OLDC*4)  /* 75776 */
__global__ void __launch_bounds__(256, 2) out_wmma_kernel(const float* __restrict__ x,
                                                          float* __restrict__ out) {
    extern __shared__ char smraw[];
    __half* S  = (__half*)smraw;
    float*  Cs = (float*)smraw;             // epilogue reuse

    const int tid = threadIdx.x, w = tid >> 5;
    const int wm = w >> 1, wn = w & 1;
    const int bs = blockIdx.x, bc = blockIdx.y, n = blockIdx.z;
    const int s0 = bs*128, c0 = bc*128;

    const float* Mfb = g_M + (size_t)n*CC*CC;
    const float* Xb  = x + (size_t)n*CC*SS;

    wmma::fragment<wmma::accumulator, 16, 16, 16, float> acc[2][4];
#pragma unroll
    for (int i = 0; i < 2; i++)
#pragma unroll
        for (int j = 0; j < 4; j++) wmma::fill_fragment(acc[i][j], 0.0f);

    const int arow = tid >> 1, apart = tid & 1;

    auto stage = [&](int st, int kb) {
        __half* Ahs = S + st*OSTR;
        __half* Als = Ahs + 128*OLDAH;
        __half* Bhs = Als + 128*OLDAH;
        __half* Bls = Bhs + 32*OLDBH;
#pragma unroll
        for (int q = 0; q < 4; q++) {
            float4 v = *(const float4*)(Mfb + (size_t)(c0 + arow)*CC + kb + apart*16 + q*4);
            int o = arow*OLDAH + apart*16 + q*4;
            split2h(v.x, Ahs[o+0], Als[o+0]); split2h(v.y, Ahs[o+1], Als[o+1]);
            split2h(v.z, Ahs[o+2], Als[o+2]); split2h(v.w, Ahs[o+3], Als[o+3]);
        }
#pragma unroll
        for (int i = 0; i < 4; i++) {
            int idx = i*256 + tid;
            int r = idx >> 5, c4 = idx & 31;
            float4 v = *(const float4*)(Xb + (size_t)(kb + r)*SS + s0 + c4*4);
            int o = r*OLDBH + c4*4;
            split2h(v.x, Bhs[o+0], Bls[o+0]); split2h(v.y, Bhs[o+1], Bls[o+1]);
            split2h(v.z, Bhs[o+2], Bls[o+2]); split2h(v.w, Bhs[o+3], Bls[o+3]);
        }
    };

    auto domma = [&](int st) {
        __half* Ahs = S + st*OSTR;
        __half* Als = Ahs + 128*OLDAH;
        __half* Bhs = Als + 128*OLDAH;
        __half* Bls = Bhs + 32*OLDBH;
#pragma unroll
        for (int ks = 0; ks < 2; ks++) {
            wmma::fragment<wmma::matrix_a, 16, 16, 16, __half, wmma::row_major> ah[2], al[2];
            wmma::fragment<wmma::matrix_b, 16, 16, 16, __half, wmma::row_major> bh[4], bl[4];
#pragma unroll
            for (int i = 0; i < 2; i++) {
                wmma::load_matrix_sync(ah[i], &Ahs[(wm*32 + i*16)*OLDAH + ks*16], OLDAH);
                wmma::load_matrix_sync(al[i], &Als[(wm*32 + i*16)*OLDAH + ks*16], OLDAH);
            }
#pragma unroll
            for (int j = 0; j < 4; j++) {
                wmma::load_matrix_sync(bh[j], &Bhs[(ks*16)*OLDBH + wn*64 + j*16], OLDBH);
                wmma::load_matrix_sync(bl[j], &Bls[(ks*16)*OLDBH + wn*64 + j*16], OLDBH);
            }
#pragma unroll
            for (int i = 0; i < 2; i++)
#pragma unroll
                for (int j = 0; j < 4; j++) {
                    wmma::mma_sync(acc[i][j], ah[i], bl[j], acc[i][j]);
                    wmma::mma_sync(acc[i][j], al[i], bh[j], acc[i][j]);
                    wmma::mma_sync(acc[i][j], ah[i], bh[j], acc[i][j]);
                }
        }
    };

    stage(0, 0);
    __syncthreads();
    int st = 0;
    for (int kb = 0; kb < CC; kb += 32) {
        if (kb + 32 < CC) stage(st ^ 1, kb + 32);
        domma(st);
        __syncthreads();
        st ^= 1;
    }

#pragma unroll
    for (int i = 0; i < 2; i++)
#pragma unroll
        for (int j = 0; j < 4; j++)
            wmma::store_matrix_sync(&Cs[(wm*32 + i*16)*OLDC + wn*64 + j*16],
                                    acc[i][j], OLDC, wmma::mem_row_major);
    __syncthreads();

    const int crow = tid >> 1, cpart = tid & 1;
    float cv = g_cv[n*CC + c0 + crow];
    float* op = out + ((size_t)n*CC + c0 + crow)*SS + s0 + cpart*64;
#pragma unroll
    for (int q = 0; q < 16; q++) {
        float4 v = *(float4*)&Cs[crow*OLDC + cpart*64 + q*4];
        v.x += cv; v.y += cv; v.z += cv; v.w += cv;
        *(float4*)(op + q*4) = v;
    }
}

// ---------------- launcher ----------------
extern "C" void kernel_launch(void* const* d_in, const int* in_sizes, int n_in,
                              void* d_out, int out_size) {
    const float* x   = (const float*)d_in[0];
    const float* Wk  = (const float*)d_in[1];
    const float* kg  = (const float*)d_in[2];
    const float* kb  = (const float*)d_in[3];
    const float* km  = (const float*)d_in[4];
    const float* kv  = (const float*)d_in[5];
    const float* Wq  = (const float*)d_in[6];
    const float* qg  = (const float*)d_in[7];
    const float* qb  = (const float*)d_in[8];
    const float* qm  = (const float*)d_in[9];
    const float* qv  = (const float*)d_in[10];
    const float* Wv  = (const float*)d_in[11];
    const float* vg  = (const float*)d_in[12];
    const float* vb  = (const float*)d_in[13];
    const float* vm  = (const float*)d_in[14];
    const float* vv  = (const float*)d_in[15];
    float* out = (float*)d_out;

    cudaFuncSetAttribute(gram_wmma_kernel, cudaFuncAttributeMaxDynamicSharedMemorySize, GRAM_SMEM);
    cudaFuncSetAttribute(out_wmma_kernel,  cudaFuncAttributeMaxDynamicSharedMemorySize, OUT_SMEM);

    prep_kernel<<<dim3(CC, 3), CC>>>(Wk, kg, kb, km, kv, Wq, qg, qb, qm, qv, Wv, vg, vb, vm, vv);
    rowsum_kernel<<<dim3(CC, BB), 256>>>(x);
    matvec_kernel<<<dim3(CC, BB), 256>>>(0);                      // u = Aq @ s
    gram_wmma_kernel<<<dim3(3, KSPLIT, BB), 256, GRAM_SMEM>>>(x); // <- profiled slot
    reduceG_kernel<<<BB*CC*CC/256, 256>>>();
    gemm256_nt_kernel<<<dim3(4, 4, BB), 256>>>(0);   // P = Aq @ G
    matvec_kernel<<<dim3(CC, BB), 256>>>(1);         // w = Ak @ s
    gemm256_nt_kernel<<<dim3(4, 4, BB), 256>>>(1);   // L = P @ Ak^T + rank-1
    softmax_kernel<<<dim3(CC, BB), 256>>>();
    gemm256_nt_kernel<<<dim3(4, 4, BB), 256>>>(2);   // M = attn @ Av + I
    matvec_kernel<<<dim3(CC, BB), 256>>>(2);         // c = attn @ bv
    out_wmma_kernel<<<dim3(SS/128, CC/128, BB), 256, OUT_SMEM>>>(x, out);
}